// round 1
// baseline (speedup 1.0000x reference)
#include <cuda_runtime.h>
#include <math.h>

// Problem constants
#define NB 4
#define NN 8192
#define NC 1024
#define NH 128
#define TOTROWS 15360   // 8192 + 4096 + 2048 + 1024 scratch rows per batch

// Scratch (device globals: no allocation allowed in kernel_launch)
__device__ float g_q[NB * NN * NH];
__device__ float g_k[NB * NN * NH];
__device__ float g_v[NB * NN * NH];
__device__ float g_o[(size_t)NB * TOTROWS * NH];
__device__ float g_d[NB * TOTROWS];

// ---------------------------------------------------------------------------
// Kernel 1: fused QKV projection.  C[32768,128] = x[32768,1024] @ W[1024,128]
// Classic 128x128x8 SGEMM, 8x8 microtile with split rows/cols (ty*4 / 64+ty*4)
// so all compute LDS are conflict-free LDS.128.
// grid = (256, 3): y selects Wq/Wk/Wv -> g_q/g_k/g_v
// ---------------------------------------------------------------------------
__global__ __launch_bounds__(256) void proj_kernel(
    const float* __restrict__ x,
    const float* __restrict__ Wq,
    const float* __restrict__ Wk,
    const float* __restrict__ Wv)
{
    const float* W;
    float* out;
    if (blockIdx.y == 0)      { W = Wq; out = g_q; }
    else if (blockIdx.y == 1) { W = Wk; out = g_k; }
    else                      { W = Wv; out = g_v; }

    __shared__ float As[8][132];   // [k][m], padded
    __shared__ float Bs[8][128];   // [k][n]

    float acc[8][8] = {};

    const int t  = threadIdx.x;
    const int tx = t & 15;
    const int ty = t >> 4;

    const int arow = t >> 1;          // 0..127
    const int ak   = (t & 1) * 4;     // 0 or 4
    const int brow = t >> 5;          // 0..7
    const int bcol = (t & 31) * 4;    // 0..124

    const size_t a_base = (size_t)(blockIdx.x * 128 + arow) * NC;

    for (int k0 = 0; k0 < NC; k0 += 8) {
        float4 av = *(const float4*)&x[a_base + k0 + ak];
        As[ak + 0][arow] = av.x;
        As[ak + 1][arow] = av.y;
        As[ak + 2][arow] = av.z;
        As[ak + 3][arow] = av.w;
        float4 bv = *(const float4*)&W[(size_t)(k0 + brow) * NH + bcol];
        *(float4*)&Bs[brow][bcol] = bv;
        __syncthreads();

        #pragma unroll
        for (int kk = 0; kk < 8; kk++) {
            float a[8], b[8];
            *(float4*)&a[0] = *(float4*)&As[kk][ty * 4];
            *(float4*)&a[4] = *(float4*)&As[kk][64 + ty * 4];
            *(float4*)&b[0] = *(float4*)&Bs[kk][tx * 4];
            *(float4*)&b[4] = *(float4*)&Bs[kk][64 + tx * 4];
            #pragma unroll
            for (int i = 0; i < 8; i++)
                #pragma unroll
                for (int j = 0; j < 8; j++)
                    acc[i][j] += a[i] * b[j];
        }
        __syncthreads();
    }

    #pragma unroll
    for (int i = 0; i < 8; i++) {
        int row = blockIdx.x * 128 + ((i < 4) ? (ty * 4 + i) : (64 + ty * 4 + i - 4));
        float* orow = out + (size_t)row * NH;
        *(float4*)&orow[tx * 4]      = make_float4(acc[i][0], acc[i][1], acc[i][2], acc[i][3]);
        *(float4*)&orow[64 + tx * 4] = make_float4(acc[i][4], acc[i][5], acc[i][6], acc[i][7]);
    }
}

// ---------------------------------------------------------------------------
// Kernel 2: causal flash attention per (batch, cfg, segment, q-block of 64).
// Q/K stored d-major in smem (LDS.128 along rows), V row-major, P transposed.
// Writes normalized o and denom=exp(lse) to scratch.
// grid = 4 * 15 * 16 = 960 blocks, 256 threads.
// ---------------------------------------------------------------------------
#define QS 68          // padded row stride for d-major tiles
#define ATTN_SMEM ((128 * QS + 128 * QS + 64 * 128 + 64 * QS) * 4)  // 119808 B

__global__ __launch_bounds__(256) void attn_kernel()
{
    extern __shared__ float sm[];
    float* Qs = sm;                  // [128][QS]  Qs[d][r]
    float* Ks = Qs + 128 * QS;       // [128][QS]  Ks[d][c]
    float* Vs = Ks + 128 * QS;       // [64][128]  Vs[k][d]
    float* Pt = Vs + 64 * 128;       // [64][QS]   Pt[k][r]

    const int blk = blockIdx.x;
    const int b   = blk / 240;
    const int rem = blk % 240;
    const int cs  = rem >> 4;
    const int qb  = rem & 15;
    int cfg, seg;
    if (cs < 8)       { cfg = 0; seg = cs; }
    else if (cs < 12) { cfg = 1; seg = cs - 8; }
    else if (cs < 14) { cfg = 2; seg = cs - 12; }
    else              { cfg = 3; seg = 0; }
    const int r = 1 << cfg;
    const int w = 1024 << cfg;

    const size_t qkv_base = (size_t)b * NN * NH;
    const int t  = threadIdx.x;
    const int tx = t & 15;
    const int ty = t >> 4;

    // --- load Q tile (d-major, pre-scaled by 1/sqrt(128)) ---
    {
        const int row = t >> 2;            // 0..63
        const int j   = qb * 64 + row;
        const size_t g = qkv_base + (size_t)(seg * w + j * r) * NH;
        const float scale = 0.08838834764831843f;
        #pragma unroll
        for (int i = 0; i < 8; i++) {
            int d = (t & 3) * 4 + i * 16;
            float4 v = *(const float4*)&g_q[g + d];
            Qs[(d + 0) * QS + row] = v.x * scale;
            Qs[(d + 1) * QS + row] = v.y * scale;
            Qs[(d + 2) * QS + row] = v.z * scale;
            Qs[(d + 3) * QS + row] = v.w * scale;
        }
    }

    float m_i[4], l_i[4], o[4][8];
    #pragma unroll
    for (int i = 0; i < 4; i++) {
        m_i[i] = -INFINITY;
        l_i[i] = 0.f;
        #pragma unroll
        for (int j = 0; j < 8; j++) o[i][j] = 0.f;
    }

    for (int kt = 0; kt <= qb; kt++) {
        __syncthreads();   // protect K/V/Pt against previous iteration's readers
        // --- load K (d-major) and V (row-major) tiles ---
        {
            const int row = t >> 2;
            const int j   = kt * 64 + row;
            const size_t g = qkv_base + (size_t)(seg * w + j * r) * NH;
            #pragma unroll
            for (int i = 0; i < 8; i++) {
                int d = (t & 3) * 4 + i * 16;
                float4 kv = *(const float4*)&g_k[g + d];
                Ks[(d + 0) * QS + row] = kv.x;
                Ks[(d + 1) * QS + row] = kv.y;
                Ks[(d + 2) * QS + row] = kv.z;
                Ks[(d + 3) * QS + row] = kv.w;
                float4 vv = *(const float4*)&g_v[g + d];
                *(float4*)&Vs[row * NH + d] = vv;
            }
        }
        __syncthreads();

        // --- S = Q @ K^T (4x4 microtile) ---
        float s[4][4] = {};
        #pragma unroll 8
        for (int d = 0; d < 128; d++) {
            float4 qv = *(float4*)(Qs + d * QS + ty * 4);
            float4 kv = *(float4*)(Ks + d * QS + tx * 4);
            float qa[4] = {qv.x, qv.y, qv.z, qv.w};
            float ka[4] = {kv.x, kv.y, kv.z, kv.w};
            #pragma unroll
            for (int i = 0; i < 4; i++)
                #pragma unroll
                for (int c = 0; c < 4; c++)
                    s[i][c] += qa[i] * ka[c];
        }

        // --- causal mask on diagonal tile ---
        if (kt == qb) {
            #pragma unroll
            for (int i = 0; i < 4; i++)
                #pragma unroll
                for (int c = 0; c < 4; c++)
                    if (tx * 4 + c > ty * 4 + i) s[i][c] = -INFINITY;
        }

        // --- online softmax (row stats shared across the 16-lane tx group) ---
        #pragma unroll
        for (int i = 0; i < 4; i++) {
            float mx = fmaxf(fmaxf(s[i][0], s[i][1]), fmaxf(s[i][2], s[i][3]));
            #pragma unroll
            for (int off = 8; off >= 1; off >>= 1)
                mx = fmaxf(mx, __shfl_xor_sync(0xffffffffu, mx, off));
            float mn = fmaxf(m_i[i], mx);
            float sc = __expf(m_i[i] - mn);
            m_i[i] = mn;
            float ps = 0.f;
            #pragma unroll
            for (int c = 0; c < 4; c++) {
                float p = __expf(s[i][c] - mn);
                s[i][c] = p;
                ps += p;
            }
            #pragma unroll
            for (int off = 8; off >= 1; off >>= 1)
                ps += __shfl_xor_sync(0xffffffffu, ps, off);
            l_i[i] = l_i[i] * sc + ps;
            #pragma unroll
            for (int j = 0; j < 8; j++) o[i][j] *= sc;
            #pragma unroll
            for (int c = 0; c < 4; c++)
                Pt[(tx * 4 + c) * QS + ty * 4 + i] = s[i][c];
        }
        __syncthreads();

        // --- O += P @ V ---
        #pragma unroll 4
        for (int k = 0; k < 64; k++) {
            float4 pv = *(float4*)(Pt + k * QS + ty * 4);
            float pa[4] = {pv.x, pv.y, pv.z, pv.w};
            float4 v0 = *(float4*)(Vs + k * NH + tx * 4);
            float4 v1 = *(float4*)(Vs + k * NH + 64 + tx * 4);
            float vb[8] = {v0.x, v0.y, v0.z, v0.w, v1.x, v1.y, v1.z, v1.w};
            #pragma unroll
            for (int i = 0; i < 4; i++)
                #pragma unroll
                for (int j = 0; j < 8; j++)
                    o[i][j] += pa[i] * vb[j];
        }
    }

    // --- epilogue: normalize, write o and denom ---
    const int cbase = 16384 - (16384 >> cfg);   // 0, 8192, 12288, 14336
    const size_t obase = (size_t)b * TOTROWS + cbase + seg * 1024 + qb * 64;
    #pragma unroll
    for (int i = 0; i < 4; i++) {
        const int row = ty * 4 + i;
        const float inv = 1.0f / l_i[i];
        float* orow = g_o + (obase + row) * NH;
        *(float4*)&orow[tx * 4] = make_float4(o[i][0] * inv, o[i][1] * inv,
                                              o[i][2] * inv, o[i][3] * inv);
        *(float4*)&orow[64 + tx * 4] = make_float4(o[i][4] * inv, o[i][5] * inv,
                                                   o[i][6] * inv, o[i][7] * inv);
        if (tx == 0)
            g_d[obase + row] = l_i[i] * __expf(m_i[i]);
    }
}

// ---------------------------------------------------------------------------
// Kernel 3: cross-config combine. One warp per (b, p); lane covers 4 h.
// out[b,p,:] = sum_cfg o_cfg * denom_cfg / denom_sum
// ---------------------------------------------------------------------------
__global__ __launch_bounds__(256) void combine_kernel(float* __restrict__ out)
{
    const int gw = (blockIdx.x * blockDim.x + threadIdx.x) >> 5;
    const int lane = threadIdx.x & 31;
    if (gw >= NB * NN) return;
    const int b = gw >> 13;
    const int p = gw & (NN - 1);

    size_t rows[4];
    float dens[4];
    int cnt = 0;
    float dsum = 0.f;
    #pragma unroll
    for (int i = 0; i < 4; i++) {
        if ((p & ((1 << i) - 1)) == 0) {
            int s = p >> (10 + i);
            int j = (p & ((1024 << i) - 1)) >> i;
            int cbase = 16384 - (16384 >> i);
            size_t row = (size_t)b * TOTROWS + cbase + s * 1024 + j;
            float d = g_d[row];
            rows[cnt] = row;
            dens[cnt] = d;
            dsum += d;
            cnt++;
        }
    }

    const int c = lane * 4;
    float4 acc = make_float4(0.f, 0.f, 0.f, 0.f);
    for (int q = 0; q < cnt; q++) {
        float wgt = dens[q] / dsum;
        float4 ov = *(const float4*)&g_o[rows[q] * NH + c];
        acc.x += ov.x * wgt;
        acc.y += ov.y * wgt;
        acc.z += ov.z * wgt;
        acc.w += ov.w * wgt;
    }
    *(float4*)&out[((size_t)b * NN + p) * NH + c] = acc;
}

// ---------------------------------------------------------------------------
extern "C" void kernel_launch(void* const* d_in, const int* in_sizes, int n_in,
                              void* d_out, int out_size)
{
    const float* x  = (const float*)d_in[0];
    const float* Wq = (const float*)d_in[1];
    const float* Wk = (const float*)d_in[2];
    const float* Wv = (const float*)d_in[3];
    float* out = (float*)d_out;

    cudaFuncSetAttribute((const void*)attn_kernel,
                         cudaFuncAttributeMaxDynamicSharedMemorySize, ATTN_SMEM);

    proj_kernel<<<dim3(256, 3), 256>>>(x, Wq, Wk, Wv);
    attn_kernel<<<960, 256, ATTN_SMEM>>>();
    combine_kernel<<<(NB * NN * 32 + 255) / 256, 256>>>(out);
}

// round 2
// speedup vs baseline: 1.1146x; 1.1146x over previous
#include <cuda_runtime.h>
#include <math.h>

// Problem constants
#define NB 4
#define NN 8192
#define NC 1024
#define NH 128
#define TOTROWS 15360   // 8192 + 4096 + 2048 + 1024 scratch rows per batch

typedef unsigned long long ull;

// Scratch (device globals: no allocation allowed in kernel_launch)
__device__ float g_q[NB * NN * NH];
__device__ float g_k[NB * NN * NH];
__device__ float g_v[NB * NN * NH];
__device__ float g_o[(size_t)NB * TOTROWS * NH];
__device__ float g_d[NB * TOTROWS];

// ---- packed f32x2 helpers (SASS FFMA2 path, fp32-exact) ----
__device__ __forceinline__ ull f2_fma(ull a, ull b, ull c) {
    ull d;
    asm("fma.rn.f32x2 %0, %1, %2, %3;" : "=l"(d) : "l"(a), "l"(b), "l"(c));
    return d;
}
__device__ __forceinline__ ull f2_mul(ull a, ull b) {
    ull d;
    asm("mul.rn.f32x2 %0, %1, %2;" : "=l"(d) : "l"(a), "l"(b));
    return d;
}
__device__ __forceinline__ ull f2_dup(float x) {
    ull d;
    unsigned int xi = __float_as_uint(x);
    asm("mov.b64 %0, {%1, %1};" : "=l"(d) : "r"(xi));
    return d;
}

union F4U { float4 f; ull u[2]; };
union UF2 { ull u; float2 f; };

// ---------------------------------------------------------------------------
// Kernel 1: fused QKV projection.  C[32768,128] = x[32768,1024] @ W[1024,128]
// 128x128x8 SGEMM, 8x8 microtile, inner product via packed fma.rn.f32x2.
// grid = (256, 3): y selects Wq/Wk/Wv -> g_q/g_k/g_v
// ---------------------------------------------------------------------------
__global__ __launch_bounds__(256) void proj_kernel(
    const float* __restrict__ x,
    const float* __restrict__ Wq,
    const float* __restrict__ Wk,
    const float* __restrict__ Wv)
{
    const float* W;
    float* out;
    if (blockIdx.y == 0)      { W = Wq; out = g_q; }
    else if (blockIdx.y == 1) { W = Wk; out = g_k; }
    else                      { W = Wv; out = g_v; }

    __shared__ float As[8][132];   // [k][m], padded
    __shared__ float Bs[8][128];   // [k][n]

    // acc2[i][jp]: row i, packed column pair jp
    // jp=0 -> cols tx*4+{0,1}, jp=1 -> tx*4+{2,3}, jp=2 -> 64+tx*4+{0,1}, jp=3 -> 64+tx*4+{2,3}
    ull acc2[8][4];
    #pragma unroll
    for (int i = 0; i < 8; i++)
        #pragma unroll
        for (int j = 0; j < 4; j++) acc2[i][j] = 0ull;

    const int t  = threadIdx.x;
    const int tx = t & 15;
    const int ty = t >> 4;

    const int arow = t >> 1;          // 0..127
    const int ak   = (t & 1) * 4;     // 0 or 4
    const int brow = t >> 5;          // 0..7
    const int bcol = (t & 31) * 4;    // 0..124

    const size_t a_base = (size_t)(blockIdx.x * 128 + arow) * NC;

    for (int k0 = 0; k0 < NC; k0 += 8) {
        float4 av = *(const float4*)&x[a_base + k0 + ak];
        As[ak + 0][arow] = av.x;
        As[ak + 1][arow] = av.y;
        As[ak + 2][arow] = av.z;
        As[ak + 3][arow] = av.w;
        float4 bv = *(const float4*)&W[(size_t)(k0 + brow) * NH + bcol];
        *(float4*)&Bs[brow][bcol] = bv;
        __syncthreads();

        #pragma unroll
        for (int kk = 0; kk < 8; kk++) {
            float a[8];
            *(float4*)&a[0] = *(float4*)&As[kk][ty * 4];
            *(float4*)&a[4] = *(float4*)&As[kk][64 + ty * 4];
            F4U b0, b1;
            b0.f = *(float4*)&Bs[kk][tx * 4];
            b1.f = *(float4*)&Bs[kk][64 + tx * 4];
            ull bp[4] = { b0.u[0], b0.u[1], b1.u[0], b1.u[1] };
            #pragma unroll
            for (int i = 0; i < 8; i++) {
                ull ad = f2_dup(a[i]);
                #pragma unroll
                for (int jp = 0; jp < 4; jp++)
                    acc2[i][jp] = f2_fma(ad, bp[jp], acc2[i][jp]);
            }
        }
        __syncthreads();
    }

    #pragma unroll
    for (int i = 0; i < 8; i++) {
        int row = blockIdx.x * 128 + ((i < 4) ? (ty * 4 + i) : (64 + ty * 4 + i - 4));
        float* orow = out + (size_t)row * NH;
        UF2 p0, p1, p2, p3;
        p0.u = acc2[i][0]; p1.u = acc2[i][1]; p2.u = acc2[i][2]; p3.u = acc2[i][3];
        *(float4*)&orow[tx * 4]      = make_float4(p0.f.x, p0.f.y, p1.f.x, p1.f.y);
        *(float4*)&orow[64 + tx * 4] = make_float4(p2.f.x, p2.f.y, p3.f.x, p3.f.y);
    }
}

// ---------------------------------------------------------------------------
// Kernel 2: causal flash attention per (batch, cfg, segment, q-block of 64).
// Q/K d-major in smem, V row-major, P transposed. GEMMs via fma.rn.f32x2.
// grid = 4 * 15 * 16 = 960 blocks, 256 threads.
// ---------------------------------------------------------------------------
#define QS 68          // padded row stride for d-major tiles
#define ATTN_SMEM ((128 * QS + 128 * QS + 64 * 128 + 64 * QS) * 4)  // 119808 B

__global__ __launch_bounds__(256) void attn_kernel()
{
    extern __shared__ float sm[];
    float* Qs = sm;                  // [128][QS]  Qs[d][r]
    float* Ks = Qs + 128 * QS;       // [128][QS]  Ks[d][c]
    float* Vs = Ks + 128 * QS;       // [64][128]  Vs[k][d]
    float* Pt = Vs + 64 * 128;       // [64][QS]   Pt[k][r]

    const int blk = blockIdx.x;
    const int b   = blk / 240;
    const int rem = blk % 240;
    const int cs  = rem >> 4;
    const int qb  = rem & 15;
    int cfg, seg;
    if (cs < 8)       { cfg = 0; seg = cs; }
    else if (cs < 12) { cfg = 1; seg = cs - 8; }
    else if (cs < 14) { cfg = 2; seg = cs - 12; }
    else              { cfg = 3; seg = 0; }
    const int r = 1 << cfg;
    const int w = 1024 << cfg;

    const size_t qkv_base = (size_t)b * NN * NH;
    const int t  = threadIdx.x;
    const int tx = t & 15;
    const int ty = t >> 4;

    // --- load Q tile (d-major, pre-scaled by 1/sqrt(128)) ---
    {
        const int row = t >> 2;            // 0..63
        const int j   = qb * 64 + row;
        const size_t g = qkv_base + (size_t)(seg * w + j * r) * NH;
        const float scale = 0.08838834764831843f;
        #pragma unroll
        for (int i = 0; i < 8; i++) {
            int d = (t & 3) * 4 + i * 16;
            float4 v = *(const float4*)&g_q[g + d];
            Qs[(d + 0) * QS + row] = v.x * scale;
            Qs[(d + 1) * QS + row] = v.y * scale;
            Qs[(d + 2) * QS + row] = v.z * scale;
            Qs[(d + 3) * QS + row] = v.w * scale;
        }
    }

    float m_i[4], l_i[4];
    ull o2[4][4];   // packed output accumulators: jp pairs as in proj
    #pragma unroll
    for (int i = 0; i < 4; i++) {
        m_i[i] = -INFINITY;
        l_i[i] = 0.f;
        #pragma unroll
        for (int j = 0; j < 4; j++) o2[i][j] = 0ull;
    }

    for (int kt = 0; kt <= qb; kt++) {
        __syncthreads();   // protect K/V/Pt against previous iteration's readers
        // --- load K (d-major) and V (row-major) tiles ---
        {
            const int row = t >> 2;
            const int j   = kt * 64 + row;
            const size_t g = qkv_base + (size_t)(seg * w + j * r) * NH;
            #pragma unroll
            for (int i = 0; i < 8; i++) {
                int d = (t & 3) * 4 + i * 16;
                float4 kv = *(const float4*)&g_k[g + d];
                Ks[(d + 0) * QS + row] = kv.x;
                Ks[(d + 1) * QS + row] = kv.y;
                Ks[(d + 2) * QS + row] = kv.z;
                Ks[(d + 3) * QS + row] = kv.w;
                float4 vv = *(const float4*)&g_v[g + d];
                *(float4*)&Vs[row * NH + d] = vv;
            }
        }
        __syncthreads();

        // --- S = Q @ K^T (4x4 microtile, packed pairs along columns) ---
        ull s2[4][2] = {{0ull,0ull},{0ull,0ull},{0ull,0ull},{0ull,0ull}};
        #pragma unroll 8
        for (int d = 0; d < 128; d++) {
            float4 qv = *(float4*)(Qs + d * QS + ty * 4);
            F4U kv; kv.f = *(float4*)(Ks + d * QS + tx * 4);
            float qa[4] = {qv.x, qv.y, qv.z, qv.w};
            #pragma unroll
            for (int i = 0; i < 4; i++) {
                ull qd = f2_dup(qa[i]);
                s2[i][0] = f2_fma(qd, kv.u[0], s2[i][0]);
                s2[i][1] = f2_fma(qd, kv.u[1], s2[i][1]);
            }
        }

        // unpack scores
        float s[4][4];
        #pragma unroll
        for (int i = 0; i < 4; i++) {
            UF2 a, bq;
            a.u = s2[i][0]; bq.u = s2[i][1];
            s[i][0] = a.f.x; s[i][1] = a.f.y; s[i][2] = bq.f.x; s[i][3] = bq.f.y;
        }

        // --- causal mask on diagonal tile ---
        if (kt == qb) {
            #pragma unroll
            for (int i = 0; i < 4; i++)
                #pragma unroll
                for (int c = 0; c < 4; c++)
                    if (tx * 4 + c > ty * 4 + i) s[i][c] = -INFINITY;
        }

        // --- online softmax (row stats shared across the 16-lane tx group) ---
        #pragma unroll
        for (int i = 0; i < 4; i++) {
            float mx = fmaxf(fmaxf(s[i][0], s[i][1]), fmaxf(s[i][2], s[i][3]));
            #pragma unroll
            for (int off = 8; off >= 1; off >>= 1)
                mx = fmaxf(mx, __shfl_xor_sync(0xffffffffu, mx, off));
            float mn = fmaxf(m_i[i], mx);
            float sc = __expf(m_i[i] - mn);
            m_i[i] = mn;
            float ps = 0.f;
            #pragma unroll
            for (int c = 0; c < 4; c++) {
                float p = __expf(s[i][c] - mn);
                s[i][c] = p;
                ps += p;
            }
            #pragma unroll
            for (int off = 8; off >= 1; off >>= 1)
                ps += __shfl_xor_sync(0xffffffffu, ps, off);
            l_i[i] = l_i[i] * sc + ps;
            ull scd = f2_dup(sc);
            #pragma unroll
            for (int j = 0; j < 4; j++) o2[i][j] = f2_mul(o2[i][j], scd);
            #pragma unroll
            for (int c = 0; c < 4; c++)
                Pt[(tx * 4 + c) * QS + ty * 4 + i] = s[i][c];
        }
        __syncthreads();

        // --- O += P @ V (packed pairs along head dim) ---
        #pragma unroll 4
        for (int k = 0; k < 64; k++) {
            float4 pv = *(float4*)(Pt + k * QS + ty * 4);
            float pa[4] = {pv.x, pv.y, pv.z, pv.w};
            F4U v0, v1;
            v0.f = *(float4*)(Vs + k * NH + tx * 4);
            v1.f = *(float4*)(Vs + k * NH + 64 + tx * 4);
            ull vp[4] = { v0.u[0], v0.u[1], v1.u[0], v1.u[1] };
            #pragma unroll
            for (int i = 0; i < 4; i++) {
                ull pd = f2_dup(pa[i]);
                #pragma unroll
                for (int jp = 0; jp < 4; jp++)
                    o2[i][jp] = f2_fma(pd, vp[jp], o2[i][jp]);
            }
        }
    }

    // --- epilogue: normalize, write o and denom ---
    const int cbase = 16384 - (16384 >> cfg);   // 0, 8192, 12288, 14336
    const size_t obase = (size_t)b * TOTROWS + cbase + seg * 1024 + qb * 64;
    #pragma unroll
    for (int i = 0; i < 4; i++) {
        const int row = ty * 4 + i;
        const float inv = 1.0f / l_i[i];
        float* orow = g_o + (obase + row) * NH;
        UF2 p0, p1, p2, p3;
        p0.u = o2[i][0]; p1.u = o2[i][1]; p2.u = o2[i][2]; p3.u = o2[i][3];
        *(float4*)&orow[tx * 4] = make_float4(p0.f.x * inv, p0.f.y * inv,
                                              p1.f.x * inv, p1.f.y * inv);
        *(float4*)&orow[64 + tx * 4] = make_float4(p2.f.x * inv, p2.f.y * inv,
                                                   p3.f.x * inv, p3.f.y * inv);
        if (tx == 0)
            g_d[obase + row] = l_i[i] * __expf(m_i[i]);
    }
}

// ---------------------------------------------------------------------------
// Kernel 3: cross-config combine. One warp per (b, p); lane covers 4 h.
// out[b,p,:] = sum_cfg o_cfg * denom_cfg / denom_sum
// ---------------------------------------------------------------------------
__global__ __launch_bounds__(256) void combine_kernel(float* __restrict__ out)
{
    const int gw = (blockIdx.x * blockDim.x + threadIdx.x) >> 5;
    const int lane = threadIdx.x & 31;
    if (gw >= NB * NN) return;
    const int b = gw >> 13;
    const int p = gw & (NN - 1);

    size_t rows[4];
    float dens[4];
    int cnt = 0;
    float dsum = 0.f;
    #pragma unroll
    for (int i = 0; i < 4; i++) {
        if ((p & ((1 << i) - 1)) == 0) {
            int s = p >> (10 + i);
            int j = (p & ((1024 << i) - 1)) >> i;
            int cbase = 16384 - (16384 >> i);
            size_t row = (size_t)b * TOTROWS + cbase + s * 1024 + j;
            float d = g_d[row];
            rows[cnt] = row;
            dens[cnt] = d;
            dsum += d;
            cnt++;
        }
    }

    const int c = lane * 4;
    float4 acc = make_float4(0.f, 0.f, 0.f, 0.f);
    for (int q = 0; q < cnt; q++) {
        float wgt = dens[q] / dsum;
        float4 ov = *(const float4*)&g_o[rows[q] * NH + c];
        acc.x += ov.x * wgt;
        acc.y += ov.y * wgt;
        acc.z += ov.z * wgt;
        acc.w += ov.w * wgt;
    }
    *(float4*)&out[((size_t)b * NN + p) * NH + c] = acc;
}

// ---------------------------------------------------------------------------
extern "C" void kernel_launch(void* const* d_in, const int* in_sizes, int n_in,
                              void* d_out, int out_size)
{
    const float* x  = (const float*)d_in[0];
    const float* Wq = (const float*)d_in[1];
    const float* Wk = (const float*)d_in[2];
    const float* Wv = (const float*)d_in[3];
    float* out = (float*)d_out;

    cudaFuncSetAttribute((const void*)attn_kernel,
                         cudaFuncAttributeMaxDynamicSharedMemorySize, ATTN_SMEM);

    proj_kernel<<<dim3(256, 3), 256>>>(x, Wq, Wk, Wv);
    attn_kernel<<<960, 256, ATTN_SMEM>>>();
    combine_kernel<<<(NB * NN * 32 + 255) / 256, 256>>>(out);
}

// round 4
// speedup vs baseline: 2.4972x; 2.2405x over previous
#include <cuda_runtime.h>
#include <cuda_bf16.h>
#include <math.h>
#include <stdint.h>

// Problem constants
#define NB 4
#define NN 8192
#define NC 1024
#define NH 128
#define TOTROWS 15360   // 8192 + 4096 + 2048 + 1024 scratch rows per batch

// Scratch (device globals: no allocation allowed in kernel_launch)
__device__ __nv_bfloat16 g_qh[NB * NN * NH], g_ql[NB * NN * NH];
__device__ __nv_bfloat16 g_kh[NB * NN * NH], g_kl[NB * NN * NH];
__device__ __nv_bfloat16 g_vh[NB * NN * NH], g_vl[NB * NN * NH];
__device__ __nv_bfloat16 g_wth[3 * 128 * 1024], g_wtl[3 * 128 * 1024]; // W^T hi/lo [w][n][k]
__device__ float g_o[(size_t)NB * TOTROWS * NH];
__device__ float g_d[NB * TOTROWS];

// ============================ helpers ============================
__device__ __forceinline__ uint32_t smem_u32(const void* p) {
    uint32_t a;
    asm("{ .reg .u64 t; cvta.to.shared.u64 t, %1; cvt.u32.u64 %0, t; }"
        : "=r"(a) : "l"(p));
    return a;
}

__device__ __forceinline__ void ldsm_x4(uint32_t r[4], uint32_t addr) {
    asm volatile("ldmatrix.sync.aligned.m8n8.x4.shared.b16 {%0,%1,%2,%3}, [%4];"
                 : "=r"(r[0]), "=r"(r[1]), "=r"(r[2]), "=r"(r[3]) : "r"(addr));
}
__device__ __forceinline__ void ldsm_x4_t(uint32_t r[4], uint32_t addr) {
    asm volatile("ldmatrix.sync.aligned.m8n8.x4.trans.shared.b16 {%0,%1,%2,%3}, [%4];"
                 : "=r"(r[0]), "=r"(r[1]), "=r"(r[2]), "=r"(r[3]) : "r"(addr));
}

// D(+=) A@B : m16n8k16 bf16 -> f32
__device__ __forceinline__ void mma16816(float c[4], const uint32_t a[4],
                                         uint32_t b0, uint32_t b1) {
    asm volatile(
        "mma.sync.aligned.m16n8k16.row.col.f32.bf16.bf16.f32 "
        "{%0,%1,%2,%3}, {%4,%5,%6,%7}, {%8,%9}, {%0,%1,%2,%3};"
        : "+f"(c[0]), "+f"(c[1]), "+f"(c[2]), "+f"(c[3])
        : "r"(a[0]), "r"(a[1]), "r"(a[2]), "r"(a[3]), "r"(b0), "r"(b1));
}

// split two fp32 into packed bf16x2 hi and lo (x = hi + lo + O(2^-16))
__device__ __forceinline__ void split2(float x, float y, uint32_t& hi, uint32_t& lo) {
    __nv_bfloat16 hx = __float2bfloat16_rn(x);
    __nv_bfloat16 hy = __float2bfloat16_rn(y);
    __nv_bfloat16 lx = __float2bfloat16_rn(x - __bfloat162float(hx));
    __nv_bfloat16 ly = __float2bfloat16_rn(y - __bfloat162float(hy));
    __nv_bfloat162 h2 = __halves2bfloat162(hx, hy);
    __nv_bfloat162 l2 = __halves2bfloat162(lx, ly);
    hi = *(uint32_t*)&h2;
    lo = *(uint32_t*)&l2;
}

// ---------------------------------------------------------------------------
// Kernel 0: transpose + split W -> g_wth/g_wtl [w][n=128][k=1024] bf16
// ---------------------------------------------------------------------------
__global__ __launch_bounds__(256) void split_w(
    const float* __restrict__ Wq, const float* __restrict__ Wk,
    const float* __restrict__ Wv)
{
    __shared__ float tile[32][33];
    const float* W = (blockIdx.z == 0) ? Wq : (blockIdx.z == 1) ? Wk : Wv;
    const int k0 = blockIdx.x * 32;
    const int n0 = blockIdx.y * 32;
    const int tx = threadIdx.x, ty = threadIdx.y;
    #pragma unroll
    for (int i = ty; i < 32; i += 8)
        tile[i][tx] = W[(size_t)(k0 + i) * NH + n0 + tx];
    __syncthreads();
    #pragma unroll
    for (int i = ty; i < 32; i += 8) {
        float v = tile[tx][i];
        __nv_bfloat16 h = __float2bfloat16_rn(v);
        __nv_bfloat16 l = __float2bfloat16_rn(v - __bfloat162float(h));
        size_t idx = (size_t)blockIdx.z * 131072 + (size_t)(n0 + i) * 1024 + k0 + tx;
        g_wth[idx] = h;
        g_wtl[idx] = l;
    }
}

// ---------------------------------------------------------------------------
// Kernel 1: QKV projection, bf16x3 mma.sync.
// CTA tile M=128, N=128, K chunks of 32. grid=(256,3) y->Wq/Wk/Wv.
// 256 threads = 8 warps, warp tile m64 x n32.
// Epilogue: split result to bf16 hi/lo arrays (q pre-scaled by 1/sqrt(128)).
// ---------------------------------------------------------------------------
#define PSTR 40                 // padded k stride (bf16 elements)
#define PBUF (128 * PSTR)       // elements per smem array
#define PROJ_SMEM_BYTES (2 * 4 * PBUF * 2)   // 2 buffers x 4 arrays

__global__ __launch_bounds__(256) void proj_mma(const float* __restrict__ x)
{
    extern __shared__ __nv_bfloat16 psm[];
    const int t = threadIdx.x;
    const int lane = t & 31;
    const int wid = t >> 5;
    const int wm = wid & 1;          // m half: wm*64
    const int wn = wid >> 1;         // n quarter: wn*32
    const size_t m0 = (size_t)blockIdx.x * 128;
    const int wsel = blockIdx.y;
    const __nv_bfloat16* wth = g_wth + (size_t)wsel * 131072;
    const __nv_bfloat16* wtl = g_wtl + (size_t)wsel * 131072;

    float acc[4][4][4];
    #pragma unroll
    for (int i = 0; i < 4; i++)
        #pragma unroll
        for (int j = 0; j < 4; j++)
            #pragma unroll
            for (int e = 0; e < 4; e++) acc[i][j][e] = 0.f;

    // staging registers
    float4 sa[4];
    uint4 sbh[2], sbl[2];

    // fill-address precompute
    const int a_row[4] = { t >> 3, (t + 256) >> 3, (t + 512) >> 3, (t + 768) >> 3 };
    const int a_c4 = (t & 7) * 4;

    auto load_stage = [&](int k0) {
        #pragma unroll
        for (int p = 0; p < 4; p++)
            sa[p] = *(const float4*)&x[(m0 + a_row[p]) * NC + k0 + a_c4];
        #pragma unroll
        for (int p = 0; p < 2; p++) {
            int idx = t + p * 256;
            int row = idx >> 2, c8 = idx & 3;
            sbh[p] = *(const uint4*)&wth[(size_t)row * 1024 + k0 + c8 * 8];
            sbl[p] = *(const uint4*)&wtl[(size_t)row * 1024 + k0 + c8 * 8];
        }
    };
    auto store_stage = [&](int buf) {
        __nv_bfloat16* AH = psm + buf * 4 * PBUF;
        __nv_bfloat16* AL = AH + PBUF;
        __nv_bfloat16* BH = AH + 2 * PBUF;
        __nv_bfloat16* BL = AH + 3 * PBUF;
        #pragma unroll
        for (int p = 0; p < 4; p++) {
            uint32_t h01, l01, h23, l23;
            split2(sa[p].x, sa[p].y, h01, l01);
            split2(sa[p].z, sa[p].w, h23, l23);
            uint32_t off = a_row[p] * PSTR + a_c4;
            *(uint2*)&AH[off] = make_uint2(h01, h23);
            *(uint2*)&AL[off] = make_uint2(l01, l23);
        }
        #pragma unroll
        for (int p = 0; p < 2; p++) {
            int idx = t + p * 256;
            int row = idx >> 2, c8 = idx & 3;
            *(uint4*)&BH[row * PSTR + c8 * 8] = sbh[p];
            *(uint4*)&BL[row * PSTR + c8 * 8] = sbl[p];
        }
    };

    const uint32_t smbase = smem_u32(psm);
    const int lr = lane & 15;
    const int lc = (lane >> 4) * 8;

    auto compute = [&](int buf) {
        const uint32_t AHb = smbase + (buf * 4 * PBUF) * 2;
        const uint32_t ALb = AHb + PBUF * 2;
        const uint32_t BHb = AHb + 2 * PBUF * 2;
        const uint32_t BLb = AHb + 3 * PBUF * 2;
        #pragma unroll
        for (int ks = 0; ks < 2; ks++) {
            uint32_t ah[4][4], al[4][4];
            #pragma unroll
            for (int i = 0; i < 4; i++) {
                uint32_t off = ((wm * 64 + i * 16 + lr) * PSTR + ks * 16 + lc) * 2;
                ldsm_x4(ah[i], AHb + off);
                ldsm_x4(al[i], ALb + off);
            }
            #pragma unroll
            for (int jj = 0; jj < 2; jj++) {
                uint32_t off = ((wn * 32 + jj * 16 + lr) * PSTR + ks * 16 + lc) * 2;
                uint32_t bh[4], bl[4];
                ldsm_x4(bh, BHb + off);
                ldsm_x4(bl, BLb + off);
                #pragma unroll
                for (int i = 0; i < 4; i++) {
                    // n-tile 2jj: frags (bh[0],bh[2]); n-tile 2jj+1: (bh[1],bh[3])
                    mma16816(acc[i][2 * jj],     ah[i], bh[0], bh[2]);
                    mma16816(acc[i][2 * jj],     al[i], bh[0], bh[2]);
                    mma16816(acc[i][2 * jj],     ah[i], bl[0], bl[2]);
                    mma16816(acc[i][2 * jj + 1], ah[i], bh[1], bh[3]);
                    mma16816(acc[i][2 * jj + 1], al[i], bh[1], bh[3]);
                    mma16816(acc[i][2 * jj + 1], ah[i], bl[1], bl[3]);
                }
            }
        }
    };

    load_stage(0);
    store_stage(0);
    __syncthreads();
    for (int c = 0; c < 32; c++) {
        if (c + 1 < 32) load_stage((c + 1) * 32);
        compute(c & 1);
        __syncthreads();
        if (c + 1 < 32) {
            store_stage((c + 1) & 1);
            __syncthreads();
        }
    }

    // epilogue: scale (q only), split to bf16 hi/lo, store
    const float scale = (wsel == 0) ? 0.08838834764831843f : 1.0f;
    __nv_bfloat16* DH = (wsel == 0) ? g_qh : (wsel == 1) ? g_kh : g_vh;
    __nv_bfloat16* DL = (wsel == 0) ? g_ql : (wsel == 1) ? g_kl : g_vl;
    #pragma unroll
    for (int i = 0; i < 4; i++) {
        #pragma unroll
        for (int j = 0; j < 4; j++) {
            const int col = wn * 32 + j * 8 + 2 * (lane & 3);
            #pragma unroll
            for (int z = 0; z < 2; z++) {
                const size_t row = m0 + wm * 64 + i * 16 + (lane >> 2) + 8 * z;
                uint32_t hi, lo;
                split2(acc[i][j][2 * z] * scale, acc[i][j][2 * z + 1] * scale, hi, lo);
                *(uint32_t*)&DH[row * NH + col] = hi;
                *(uint32_t*)&DL[row * NH + col] = lo;
            }
        }
    }
}

// ---------------------------------------------------------------------------
// Kernel 2: causal flash attention, bf16x3 mma.sync.
// grid = 960 (b, cfg, seg, qb-of-64), 128 threads (4 warps x 16 q rows).
// ---------------------------------------------------------------------------
#define ASTR 136                        // padded d/key stride
#define ATILE (64 * ASTR)               // elements per smem array
#define ATTN_SMEM_BYTES (6 * ATILE * 2) // QH QL KH KL VH VL

__global__ __launch_bounds__(128) void attn_mma()
{
    extern __shared__ __nv_bfloat16 asm_[];
    __nv_bfloat16* QH = asm_;
    __nv_bfloat16* QL = QH + ATILE;
    __nv_bfloat16* KH = QH + 2 * ATILE;
    __nv_bfloat16* KL = QH + 3 * ATILE;
    __nv_bfloat16* VH = QH + 4 * ATILE;
    __nv_bfloat16* VL = QH + 5 * ATILE;

    const int blk = blockIdx.x;
    const int b   = blk / 240;
    const int rem = blk % 240;
    const int cs  = rem >> 4;
    const int qb  = rem & 15;
    int cfg, seg;
    if (cs < 8)       { cfg = 0; seg = cs; }
    else if (cs < 12) { cfg = 1; seg = cs - 8; }
    else if (cs < 14) { cfg = 2; seg = cs - 12; }
    else              { cfg = 3; seg = 0; }
    const int rr = 1 << cfg;
    const int ww = 1024 << cfg;

    const int t = threadIdx.x;
    const int lane = t & 31;
    const int w = t >> 5;               // warp id: q rows w*16..w*16+15
    const size_t tok0 = (size_t)b * NN + seg * ww;

    // ---- load Q tile (hi/lo) : 64 rows x 128 d ----
    #pragma unroll
    for (int i = 0; i < 8; i++) {
        int idx = t + i * 128;           // 0..1023
        int row = idx >> 4;
        int c = idx & 15;
        size_t src = (tok0 + (size_t)(qb * 64 + row) * rr) * NH + c * 8;
        *(uint4*)&QH[row * ASTR + c * 8] = *(const uint4*)&g_qh[src];
        *(uint4*)&QL[row * ASTR + c * 8] = *(const uint4*)&g_ql[src];
    }

    float o[16][4];
    #pragma unroll
    for (int j = 0; j < 16; j++)
        #pragma unroll
        for (int e = 0; e < 4; e++) o[j][e] = 0.f;
    float m_i[2] = { -INFINITY, -INFINITY };
    float l_i[2] = { 0.f, 0.f };

    const uint32_t sb = smem_u32(asm_);
    const uint32_t QHb = sb, QLb = sb + ATILE * 2;
    const uint32_t KHb = sb + 2 * ATILE * 2, KLb = sb + 3 * ATILE * 2;
    const uint32_t VHb = sb + 4 * ATILE * 2, VLb = sb + 5 * ATILE * 2;
    const int lr = lane & 15;
    const int lc = (lane >> 4) * 8;

    for (int kt = 0; kt <= qb; kt++) {
        __syncthreads();
        // ---- load K/V tiles (hi/lo) ----
        #pragma unroll
        for (int i = 0; i < 8; i++) {
            int idx = t + i * 128;
            int row = idx >> 4;
            int c = idx & 15;
            size_t src = (tok0 + (size_t)(kt * 64 + row) * rr) * NH + c * 8;
            *(uint4*)&KH[row * ASTR + c * 8] = *(const uint4*)&g_kh[src];
            *(uint4*)&KL[row * ASTR + c * 8] = *(const uint4*)&g_kl[src];
            *(uint4*)&VH[row * ASTR + c * 8] = *(const uint4*)&g_vh[src];
            *(uint4*)&VL[row * ASTR + c * 8] = *(const uint4*)&g_vl[src];
        }
        __syncthreads();

        // ---- S = Q @ K^T : 8 n-tiles of 8 keys ----
        float s[8][4];
        #pragma unroll
        for (int j = 0; j < 8; j++)
            #pragma unroll
            for (int e = 0; e < 4; e++) s[j][e] = 0.f;

        #pragma unroll
        for (int ks = 0; ks < 8; ks++) {
            uint32_t qh[4], ql[4];
            {
                uint32_t off = ((w * 16 + lr) * ASTR + ks * 16 + lc) * 2;
                ldsm_x4(qh, QHb + off);
                ldsm_x4(ql, QLb + off);
            }
            #pragma unroll
            for (int jj = 0; jj < 4; jj++) {
                uint32_t off = ((jj * 16 + lr) * ASTR + ks * 16 + lc) * 2;
                uint32_t kh[4], kl[4];
                ldsm_x4(kh, KHb + off);
                ldsm_x4(kl, KLb + off);
                mma16816(s[2 * jj],     qh, kh[0], kh[2]);
                mma16816(s[2 * jj],     ql, kh[0], kh[2]);
                mma16816(s[2 * jj],     qh, kl[0], kl[2]);
                mma16816(s[2 * jj + 1], qh, kh[1], kh[3]);
                mma16816(s[2 * jj + 1], ql, kh[1], kh[3]);
                mma16816(s[2 * jj + 1], qh, kl[1], kl[3]);
            }
        }

        // ---- causal mask on diagonal tile ----
        if (kt == qb) {
            #pragma unroll
            for (int j = 0; j < 8; j++)
                #pragma unroll
                for (int z = 0; z < 2; z++) {
                    int row = w * 16 + (lane >> 2) + 8 * z;
                    int col = j * 8 + 2 * (lane & 3);
                    if (col > row)     s[j][2 * z]     = -INFINITY;
                    if (col + 1 > row) s[j][2 * z + 1] = -INFINITY;
                }
        }

        // ---- online softmax (2 rows per thread; quad shares a row) ----
        #pragma unroll
        for (int z = 0; z < 2; z++) {
            float mx = -INFINITY;
            #pragma unroll
            for (int j = 0; j < 8; j++)
                mx = fmaxf(mx, fmaxf(s[j][2 * z], s[j][2 * z + 1]));
            mx = fmaxf(mx, __shfl_xor_sync(0xffffffffu, mx, 1));
            mx = fmaxf(mx, __shfl_xor_sync(0xffffffffu, mx, 2));
            float mn = fmaxf(m_i[z], mx);
            float sc = __expf(m_i[z] - mn);
            m_i[z] = mn;
            float ps = 0.f;
            #pragma unroll
            for (int j = 0; j < 8; j++) {
                float p0 = __expf(s[j][2 * z] - mn);
                float p1 = __expf(s[j][2 * z + 1] - mn);
                s[j][2 * z] = p0;
                s[j][2 * z + 1] = p1;
                ps += p0 + p1;
            }
            ps += __shfl_xor_sync(0xffffffffu, ps, 1);
            ps += __shfl_xor_sync(0xffffffffu, ps, 2);
            l_i[z] = l_i[z] * sc + ps;
            #pragma unroll
            for (int j = 0; j < 16; j++) {
                o[j][2 * z] *= sc;
                o[j][2 * z + 1] *= sc;
            }
        }

        // ---- O += P @ V ----
        #pragma unroll
        for (int kk = 0; kk < 4; kk++) {
            uint32_t ph[4], pl[4];
            split2(s[2 * kk][0],     s[2 * kk][1],     ph[0], pl[0]);
            split2(s[2 * kk][2],     s[2 * kk][3],     ph[1], pl[1]);
            split2(s[2 * kk + 1][0], s[2 * kk + 1][1], ph[2], pl[2]);
            split2(s[2 * kk + 1][2], s[2 * kk + 1][3], ph[3], pl[3]);
            #pragma unroll
            for (int jj = 0; jj < 8; jj++) {
                uint32_t off = ((kk * 16 + lr) * ASTR + jj * 16 + lc) * 2;
                uint32_t vh[4], vl[4];
                ldsm_x4_t(vh, VHb + off);
                ldsm_x4_t(vl, VLb + off);
                mma16816(o[2 * jj],     ph, vh[0], vh[1]);
                mma16816(o[2 * jj],     pl, vh[0], vh[1]);
                mma16816(o[2 * jj],     ph, vl[0], vl[1]);
                mma16816(o[2 * jj + 1], ph, vh[2], vh[3]);
                mma16816(o[2 * jj + 1], pl, vh[2], vh[3]);
                mma16816(o[2 * jj + 1], ph, vl[2], vl[3]);
            }
        }
    }

    // ---- epilogue: normalize, write o and denom ----
    const int cbase = 16384 - (16384 >> cfg);
    const size_t obase = (size_t)b * TOTROWS + cbase + seg * 1024 + qb * 64;
    #pragma unroll
    for (int z = 0; z < 2; z++) {
        const size_t row = obase + w * 16 + (lane >> 2) + 8 * z;
        const float inv = 1.0f / l_i[z];
        #pragma unroll
        for (int j = 0; j < 16; j++) {
            const int col = j * 8 + 2 * (lane & 3);
            *(float2*)&g_o[row * NH + col] =
                make_float2(o[j][2 * z] * inv, o[j][2 * z + 1] * inv);
        }
        if ((lane & 3) == 0)
            g_d[row] = l_i[z] * __expf(m_i[z]);
    }
}

// ---------------------------------------------------------------------------
// Kernel 3: cross-config combine. One warp per (b, p); lane covers 4 h.
// ---------------------------------------------------------------------------
__global__ __launch_bounds__(256) void combine_kernel(float* __restrict__ out)
{
    const int gw = (blockIdx.x * blockDim.x + threadIdx.x) >> 5;
    const int lane = threadIdx.x & 31;
    if (gw >= NB * NN) return;
    const int b = gw >> 13;
    const int p = gw & (NN - 1);

    size_t rows[4];
    float dens[4];
    int cnt = 0;
    float dsum = 0.f;
    #pragma unroll
    for (int i = 0; i < 4; i++) {
        if ((p & ((1 << i) - 1)) == 0) {
            int s = p >> (10 + i);
            int j = (p & ((1024 << i) - 1)) >> i;
            int cbase = 16384 - (16384 >> i);
            size_t row = (size_t)b * TOTROWS + cbase + s * 1024 + j;
            float d = g_d[row];
            rows[cnt] = row;
            dens[cnt] = d;
            dsum += d;
            cnt++;
        }
    }

    const int c = lane * 4;
    float4 acc = make_float4(0.f, 0.f, 0.f, 0.f);
    for (int q = 0; q < cnt; q++) {
        float wgt = dens[q] / dsum;
        float4 ov = *(const float4*)&g_o[rows[q] * NH + c];
        acc.x += ov.x * wgt;
        acc.y += ov.y * wgt;
        acc.z += ov.z * wgt;
        acc.w += ov.w * wgt;
    }
    *(float4*)&out[((size_t)b * NN + p) * NH + c] = acc;
}

// ---------------------------------------------------------------------------
extern "C" void kernel_launch(void* const* d_in, const int* in_sizes, int n_in,
                              void* d_out, int out_size)
{
    const float* x  = (const float*)d_in[0];
    const float* Wq = (const float*)d_in[1];
    const float* Wk = (const float*)d_in[2];
    const float* Wv = (const float*)d_in[3];
    float* out = (float*)d_out;

    cudaFuncSetAttribute((const void*)proj_mma,
                         cudaFuncAttributeMaxDynamicSharedMemorySize, PROJ_SMEM_BYTES);
    cudaFuncSetAttribute((const void*)attn_mma,
                         cudaFuncAttributeMaxDynamicSharedMemorySize, ATTN_SMEM_BYTES);

    split_w<<<dim3(32, 4, 3), dim3(32, 8)>>>(Wq, Wk, Wv);
    proj_mma<<<dim3(256, 3), 256, PROJ_SMEM_BYTES>>>(x);
    attn_mma<<<960, 128, ATTN_SMEM_BYTES>>>();
    combine_kernel<<<(NB * NN * 32 + 255) / 256, 256>>>(out);
}

// round 5
// speedup vs baseline: 2.7751x; 1.1113x over previous
#include <cuda_runtime.h>
#include <cuda_bf16.h>
#include <math.h>
#include <stdint.h>

// Problem constants
#define NB 4
#define NN 8192
#define NC 1024
#define NH 128
#define TOTROWS 15360   // 8192 + 4096 + 2048 + 1024 scratch rows per batch

// Scratch (device globals: no allocation allowed in kernel_launch)
__device__ __nv_bfloat16 g_qh[NB * NN * NH], g_ql[NB * NN * NH];
__device__ __nv_bfloat16 g_kh[NB * NN * NH], g_kl[NB * NN * NH];
__device__ __nv_bfloat16 g_vh[NB * NN * NH], g_vl[NB * NN * NH];
__device__ __nv_bfloat16 g_wth[3 * 128 * 1024], g_wtl[3 * 128 * 1024]; // W^T hi/lo [w][n][k]
__device__ float g_o[(size_t)NB * TOTROWS * NH];
__device__ float g_d[NB * TOTROWS];

// ============================ helpers ============================
__device__ __forceinline__ uint32_t smem_u32(const void* p) {
    uint32_t a;
    asm("{ .reg .u64 t; cvta.to.shared.u64 t, %1; cvt.u32.u64 %0, t; }"
        : "=r"(a) : "l"(p));
    return a;
}

__device__ __forceinline__ void ldsm_x4(uint32_t r[4], uint32_t addr) {
    asm volatile("ldmatrix.sync.aligned.m8n8.x4.shared.b16 {%0,%1,%2,%3}, [%4];"
                 : "=r"(r[0]), "=r"(r[1]), "=r"(r[2]), "=r"(r[3]) : "r"(addr));
}
__device__ __forceinline__ void ldsm_x4_t(uint32_t r[4], uint32_t addr) {
    asm volatile("ldmatrix.sync.aligned.m8n8.x4.trans.shared.b16 {%0,%1,%2,%3}, [%4];"
                 : "=r"(r[0]), "=r"(r[1]), "=r"(r[2]), "=r"(r[3]) : "r"(addr));
}

// D(+=) A@B : m16n8k16 bf16 -> f32
__device__ __forceinline__ void mma16816(float c[4], const uint32_t a[4],
                                         uint32_t b0, uint32_t b1) {
    asm volatile(
        "mma.sync.aligned.m16n8k16.row.col.f32.bf16.bf16.f32 "
        "{%0,%1,%2,%3}, {%4,%5,%6,%7}, {%8,%9}, {%0,%1,%2,%3};"
        : "+f"(c[0]), "+f"(c[1]), "+f"(c[2]), "+f"(c[3])
        : "r"(a[0]), "r"(a[1]), "r"(a[2]), "r"(a[3]), "r"(b0), "r"(b1));
}

// split two fp32 into packed bf16x2 hi and lo (x = hi + lo + O(2^-16))
__device__ __forceinline__ void split2(float x, float y, uint32_t& hi, uint32_t& lo) {
    __nv_bfloat16 hx = __float2bfloat16_rn(x);
    __nv_bfloat16 hy = __float2bfloat16_rn(y);
    __nv_bfloat16 lx = __float2bfloat16_rn(x - __bfloat162float(hx));
    __nv_bfloat16 ly = __float2bfloat16_rn(y - __bfloat162float(hy));
    __nv_bfloat162 h2 = __halves2bfloat162(hx, hy);
    __nv_bfloat162 l2 = __halves2bfloat162(lx, ly);
    hi = *(uint32_t*)&h2;
    lo = *(uint32_t*)&l2;
}

// cp.async helpers
__device__ __forceinline__ void cp16(uint32_t dst, const void* src) {
    asm volatile("cp.async.cg.shared.global [%0], [%1], 16;" :: "r"(dst), "l"(src));
}
__device__ __forceinline__ void cp_commit() {
    asm volatile("cp.async.commit_group;" ::: "memory");
}
template <int N>
__device__ __forceinline__ void cp_wait() {
    asm volatile("cp.async.wait_group %0;" :: "n"(N) : "memory");
}

// ---------------------------------------------------------------------------
// Kernel 0: transpose + split W -> g_wth/g_wtl [w][n=128][k=1024] bf16
// ---------------------------------------------------------------------------
__global__ __launch_bounds__(256) void split_w(
    const float* __restrict__ Wq, const float* __restrict__ Wk,
    const float* __restrict__ Wv)
{
    __shared__ float tile[32][33];
    const float* W = (blockIdx.z == 0) ? Wq : (blockIdx.z == 1) ? Wk : Wv;
    const int k0 = blockIdx.x * 32;
    const int n0 = blockIdx.y * 32;
    const int tx = threadIdx.x, ty = threadIdx.y;
    #pragma unroll
    for (int i = ty; i < 32; i += 8)
        tile[i][tx] = W[(size_t)(k0 + i) * NH + n0 + tx];
    __syncthreads();
    #pragma unroll
    for (int i = ty; i < 32; i += 8) {
        float v = tile[tx][i];
        __nv_bfloat16 h = __float2bfloat16_rn(v);
        __nv_bfloat16 l = __float2bfloat16_rn(v - __bfloat162float(h));
        size_t idx = (size_t)blockIdx.z * 131072 + (size_t)(n0 + i) * 1024 + k0 + tx;
        g_wth[idx] = h;
        g_wtl[idx] = l;
    }
}

// ---------------------------------------------------------------------------
// Kernel 1: QKV projection, bf16x3 mma.sync.
// CTA tile M=128, N=128, K chunks of 32. grid=(256,3) y->Wq/Wk/Wv.
// Single __syncthreads per chunk:
//   iter c: store(c->buf c&1); SYNC; load regs(c+1); compute(buf c&1)
// Safety: store(c) vs compute(c-1) touch different buffers; store(c) vs
// compute(c-2) (same buffer) are separated by the sync in iter c-1.
// ---------------------------------------------------------------------------
#define PSTR 40                 // padded k stride (bf16 elements)
#define PBUF (128 * PSTR)       // elements per smem array
#define PROJ_SMEM_BYTES (2 * 4 * PBUF * 2)   // 2 buffers x 4 arrays

__global__ __launch_bounds__(256) void proj_mma(const float* __restrict__ x)
{
    extern __shared__ __nv_bfloat16 psm[];
    const int t = threadIdx.x;
    const int lane = t & 31;
    const int wid = t >> 5;
    const int wm = wid & 1;          // m half: wm*64
    const int wn = wid >> 1;         // n quarter: wn*32
    const size_t m0 = (size_t)blockIdx.x * 128;
    const int wsel = blockIdx.y;
    const __nv_bfloat16* wth = g_wth + (size_t)wsel * 131072;
    const __nv_bfloat16* wtl = g_wtl + (size_t)wsel * 131072;

    float acc[4][4][4];
    #pragma unroll
    for (int i = 0; i < 4; i++)
        #pragma unroll
        for (int j = 0; j < 4; j++)
            #pragma unroll
            for (int e = 0; e < 4; e++) acc[i][j][e] = 0.f;

    // staging registers
    float4 sa[4];
    uint4 sbh[2], sbl[2];

    const int a_row[4] = { t >> 3, (t + 256) >> 3, (t + 512) >> 3, (t + 768) >> 3 };
    const int a_c4 = (t & 7) * 4;

    auto load_stage = [&](int k0) {
        #pragma unroll
        for (int p = 0; p < 4; p++)
            sa[p] = *(const float4*)&x[(m0 + a_row[p]) * NC + k0 + a_c4];
        #pragma unroll
        for (int p = 0; p < 2; p++) {
            int idx = t + p * 256;
            int row = idx >> 2, c8 = idx & 3;
            sbh[p] = *(const uint4*)&wth[(size_t)row * 1024 + k0 + c8 * 8];
            sbl[p] = *(const uint4*)&wtl[(size_t)row * 1024 + k0 + c8 * 8];
        }
    };
    auto store_stage = [&](int buf) {
        __nv_bfloat16* AH = psm + buf * 4 * PBUF;
        __nv_bfloat16* AL = AH + PBUF;
        __nv_bfloat16* BH = AH + 2 * PBUF;
        __nv_bfloat16* BL = AH + 3 * PBUF;
        #pragma unroll
        for (int p = 0; p < 4; p++) {
            uint32_t h01, l01, h23, l23;
            split2(sa[p].x, sa[p].y, h01, l01);
            split2(sa[p].z, sa[p].w, h23, l23);
            uint32_t off = a_row[p] * PSTR + a_c4;
            *(uint2*)&AH[off] = make_uint2(h01, h23);
            *(uint2*)&AL[off] = make_uint2(l01, l23);
        }
        #pragma unroll
        for (int p = 0; p < 2; p++) {
            int idx = t + p * 256;
            int row = idx >> 2, c8 = idx & 3;
            *(uint4*)&BH[row * PSTR + c8 * 8] = sbh[p];
            *(uint4*)&BL[row * PSTR + c8 * 8] = sbl[p];
        }
    };

    const uint32_t smbase = smem_u32(psm);
    const int lr = lane & 15;
    const int lc = (lane >> 4) * 8;

    auto compute = [&](int buf) {
        const uint32_t AHb = smbase + (buf * 4 * PBUF) * 2;
        const uint32_t ALb = AHb + PBUF * 2;
        const uint32_t BHb = AHb + 2 * PBUF * 2;
        const uint32_t BLb = AHb + 3 * PBUF * 2;
        #pragma unroll
        for (int ks = 0; ks < 2; ks++) {
            uint32_t ah[4][4], al[4][4];
            #pragma unroll
            for (int i = 0; i < 4; i++) {
                uint32_t off = ((wm * 64 + i * 16 + lr) * PSTR + ks * 16 + lc) * 2;
                ldsm_x4(ah[i], AHb + off);
                ldsm_x4(al[i], ALb + off);
            }
            #pragma unroll
            for (int jj = 0; jj < 2; jj++) {
                uint32_t off = ((wn * 32 + jj * 16 + lr) * PSTR + ks * 16 + lc) * 2;
                uint32_t bh[4], bl[4];
                ldsm_x4(bh, BHb + off);
                ldsm_x4(bl, BLb + off);
                #pragma unroll
                for (int i = 0; i < 4; i++) {
                    mma16816(acc[i][2 * jj],     ah[i], bh[0], bh[2]);
                    mma16816(acc[i][2 * jj],     al[i], bh[0], bh[2]);
                    mma16816(acc[i][2 * jj],     ah[i], bl[0], bl[2]);
                    mma16816(acc[i][2 * jj + 1], ah[i], bh[1], bh[3]);
                    mma16816(acc[i][2 * jj + 1], al[i], bh[1], bh[3]);
                    mma16816(acc[i][2 * jj + 1], ah[i], bl[1], bl[3]);
                }
            }
        }
    };

    load_stage(0);
    for (int c = 0; c < 32; c++) {
        store_stage(c & 1);
        __syncthreads();
        if (c + 1 < 32) load_stage((c + 1) * 32);
        compute(c & 1);
    }

    // epilogue: scale (q only), split to bf16 hi/lo, store
    const float scale = (wsel == 0) ? 0.08838834764831843f : 1.0f;
    __nv_bfloat16* DH = (wsel == 0) ? g_qh : (wsel == 1) ? g_kh : g_vh;
    __nv_bfloat16* DL = (wsel == 0) ? g_ql : (wsel == 1) ? g_kl : g_vl;
    #pragma unroll
    for (int i = 0; i < 4; i++) {
        #pragma unroll
        for (int j = 0; j < 4; j++) {
            const int col = wn * 32 + j * 8 + 2 * (lane & 3);
            #pragma unroll
            for (int z = 0; z < 2; z++) {
                const size_t row = m0 + wm * 64 + i * 16 + (lane >> 2) + 8 * z;
                uint32_t hi, lo;
                split2(acc[i][j][2 * z] * scale, acc[i][j][2 * z + 1] * scale, hi, lo);
                *(uint32_t*)&DH[row * NH + col] = hi;
                *(uint32_t*)&DL[row * NH + col] = lo;
            }
        }
    }
}

// ---------------------------------------------------------------------------
// Kernel 2: causal flash attention, bf16x3 mma.sync.
// 128-row Q tiles, 8 warps (256 thr), cp.async double-buffered K/V (64-row).
// grid = 480 blocks ordered heavy-first (qb descending).
// ---------------------------------------------------------------------------
#define ASTR 136                        // padded d/key stride (bf16 elements)
#define QTILE (128 * ASTR)
#define KTILE (64 * ASTR)
#define ATTN_SMEM_BYTES ((2 * QTILE + 8 * KTILE) * 2)   // 208896 B

__global__ __launch_bounds__(256) void attn_mma()
{
    extern __shared__ __nv_bfloat16 asm_[];
    const int blk = blockIdx.x;
    const int qb  = 7 - blk / 60;       // heavy tiles first
    const int t2  = blk % 60;
    const int b   = t2 / 15;
    const int cs  = t2 % 15;
    int cfg, seg;
    if (cs < 8)       { cfg = 0; seg = cs; }
    else if (cs < 12) { cfg = 1; seg = cs - 8; }
    else if (cs < 14) { cfg = 2; seg = cs - 12; }
    else              { cfg = 3; seg = 0; }
    const int rr = 1 << cfg;
    const int ww = 1024 << cfg;

    const int t = threadIdx.x;
    const int lane = t & 31;
    const int w = t >> 5;               // warp id: q rows w*16..w*16+15 of 128
    const size_t tok0 = (size_t)b * NN + seg * ww;

    const uint32_t sb = smem_u32(asm_);
    const uint32_t QHb = sb;
    const uint32_t QLb = sb + QTILE * 2;

    // ---- issue Q tile fill (hi/lo) via cp.async : part of group 0 ----
    #pragma unroll
    for (int i = 0; i < 8; i++) {
        int idx = t + i * 256;           // 0..2047
        int row = idx >> 4;              // 0..127
        int c = idx & 15;
        size_t src = (tok0 + (size_t)(qb * 128 + row) * rr) * NH + c * 8;
        uint32_t d = (row * ASTR + c * 8) * 2;
        cp16(QHb + d, g_qh + src);
        cp16(QLb + d, g_ql + src);
    }

    auto issue_kv = [&](int kt, int buf) {
        const uint32_t base = sb + (2 * QTILE + buf * 4 * KTILE) * 2;
        #pragma unroll
        for (int i = 0; i < 4; i++) {
            int idx = t + i * 256;        // 0..1023
            int row = idx >> 4;           // 0..63
            int c = idx & 15;
            size_t src = (tok0 + (size_t)(kt * 64 + row) * rr) * NH + c * 8;
            uint32_t d = (row * ASTR + c * 8) * 2;
            cp16(base + d,                 g_kh + src);
            cp16(base + KTILE * 2 + d,     g_kl + src);
            cp16(base + 2 * KTILE * 2 + d, g_vh + src);
            cp16(base + 3 * KTILE * 2 + d, g_vl + src);
        }
    };

    const int L = 2 * qb + 1;            // last key tile (>=1 always)
    issue_kv(0, 0);
    cp_commit();                          // group: Q + KV0
    issue_kv(1, 1);
    cp_commit();                          // group: KV1

    float o[16][4];
    #pragma unroll
    for (int j = 0; j < 16; j++)
        #pragma unroll
        for (int e = 0; e < 4; e++) o[j][e] = 0.f;
    float m_i[2] = { -INFINITY, -INFINITY };
    float l_i[2] = { 0.f, 0.f };

    const int lr = lane & 15;
    const int lc = (lane >> 4) * 8;

    for (int kt = 0; kt <= L; kt++) {
        if (kt < L) cp_wait<1>(); else cp_wait<0>();
        __syncthreads();

        const uint32_t KVB = sb + (2 * QTILE + (kt & 1) * 4 * KTILE) * 2;
        const uint32_t KHb = KVB;
        const uint32_t KLb = KVB + KTILE * 2;
        const uint32_t VHb = KVB + 2 * KTILE * 2;
        const uint32_t VLb = KVB + 3 * KTILE * 2;

        // skip warp-tiles that are fully above the causal diagonal
        const bool active = (qb * 128 + w * 16 + 15) >= kt * 64;
        if (active) {
            // ---- S = Q @ K^T : 8 n-tiles of 8 keys ----
            float s[8][4];
            #pragma unroll
            for (int j = 0; j < 8; j++)
                #pragma unroll
                for (int e = 0; e < 4; e++) s[j][e] = 0.f;

            #pragma unroll
            for (int ks = 0; ks < 8; ks++) {
                uint32_t qh[4], ql[4];
                {
                    uint32_t off = ((w * 16 + lr) * ASTR + ks * 16 + lc) * 2;
                    ldsm_x4(qh, QHb + off);
                    ldsm_x4(ql, QLb + off);
                }
                #pragma unroll
                for (int jj = 0; jj < 4; jj++) {
                    uint32_t off = ((jj * 16 + lr) * ASTR + ks * 16 + lc) * 2;
                    uint32_t kh[4], kl[4];
                    ldsm_x4(kh, KHb + off);
                    ldsm_x4(kl, KLb + off);
                    mma16816(s[2 * jj],     qh, kh[0], kh[2]);
                    mma16816(s[2 * jj],     ql, kh[0], kh[2]);
                    mma16816(s[2 * jj],     qh, kl[0], kl[2]);
                    mma16816(s[2 * jj + 1], qh, kh[1], kh[3]);
                    mma16816(s[2 * jj + 1], ql, kh[1], kh[3]);
                    mma16816(s[2 * jj + 1], qh, kl[1], kl[3]);
                }
            }

            // ---- causal mask (only tiles overlapping the diagonal) ----
            if (kt >= 2 * qb) {
                #pragma unroll
                for (int j = 0; j < 8; j++)
                    #pragma unroll
                    for (int z = 0; z < 2; z++) {
                        int gq = qb * 128 + w * 16 + (lane >> 2) + 8 * z;
                        int gk = kt * 64 + j * 8 + 2 * (lane & 3);
                        if (gk > gq)     s[j][2 * z]     = -INFINITY;
                        if (gk + 1 > gq) s[j][2 * z + 1] = -INFINITY;
                    }
            }

            // ---- online softmax (2 rows per thread; quad shares a row) ----
            #pragma unroll
            for (int z = 0; z < 2; z++) {
                float mx = -INFINITY;
                #pragma unroll
                for (int j = 0; j < 8; j++)
                    mx = fmaxf(mx, fmaxf(s[j][2 * z], s[j][2 * z + 1]));
                mx = fmaxf(mx, __shfl_xor_sync(0xffffffffu, mx, 1));
                mx = fmaxf(mx, __shfl_xor_sync(0xffffffffu, mx, 2));
                float mn = fmaxf(m_i[z], mx);
                float sc = __expf(m_i[z] - mn);
                m_i[z] = mn;
                float ps = 0.f;
                #pragma unroll
                for (int j = 0; j < 8; j++) {
                    float p0 = __expf(s[j][2 * z] - mn);
                    float p1 = __expf(s[j][2 * z + 1] - mn);
                    s[j][2 * z] = p0;
                    s[j][2 * z + 1] = p1;
                    ps += p0 + p1;
                }
                ps += __shfl_xor_sync(0xffffffffu, ps, 1);
                ps += __shfl_xor_sync(0xffffffffu, ps, 2);
                l_i[z] = l_i[z] * sc + ps;
                #pragma unroll
                for (int j = 0; j < 16; j++) {
                    o[j][2 * z] *= sc;
                    o[j][2 * z + 1] *= sc;
                }
            }

            // ---- O += P @ V ----
            #pragma unroll
            for (int kk = 0; kk < 4; kk++) {
                uint32_t ph[4], pl[4];
                split2(s[2 * kk][0],     s[2 * kk][1],     ph[0], pl[0]);
                split2(s[2 * kk][2],     s[2 * kk][3],     ph[1], pl[1]);
                split2(s[2 * kk + 1][0], s[2 * kk + 1][1], ph[2], pl[2]);
                split2(s[2 * kk + 1][2], s[2 * kk + 1][3], ph[3], pl[3]);
                #pragma unroll
                for (int jj = 0; jj < 8; jj++) {
                    uint32_t off = ((kk * 16 + lr) * ASTR + jj * 16 + lc) * 2;
                    uint32_t vh[4], vl[4];
                    ldsm_x4_t(vh, VHb + off);
                    ldsm_x4_t(vl, VLb + off);
                    mma16816(o[2 * jj],     ph, vh[0], vh[1]);
                    mma16816(o[2 * jj],     pl, vh[0], vh[1]);
                    mma16816(o[2 * jj],     ph, vl[0], vl[1]);
                    mma16816(o[2 * jj + 1], ph, vh[2], vh[3]);
                    mma16816(o[2 * jj + 1], pl, vh[2], vh[3]);
                    mma16816(o[2 * jj + 1], ph, vl[2], vl[3]);
                }
            }
        }

        __syncthreads();   // all warps done with buf (kt&1) before refill
        if (kt + 2 <= L) {
            issue_kv(kt + 2, kt & 1);
            cp_commit();
        }
    }

    // ---- epilogue: normalize, write o and denom ----
    const int cbase = 16384 - (16384 >> cfg);
    const size_t obase = (size_t)b * TOTROWS + cbase + seg * 1024 + qb * 128;
    #pragma unroll
    for (int z = 0; z < 2; z++) {
        const size_t row = obase + w * 16 + (lane >> 2) + 8 * z;
        const float inv = 1.0f / l_i[z];
        #pragma unroll
        for (int j = 0; j < 16; j++) {
            const int col = j * 8 + 2 * (lane & 3);
            *(float2*)&g_o[row * NH + col] =
                make_float2(o[j][2 * z] * inv, o[j][2 * z + 1] * inv);
        }
        if ((lane & 3) == 0)
            g_d[row] = l_i[z] * __expf(m_i[z]);
    }
}

// ---------------------------------------------------------------------------
// Kernel 3: cross-config combine. One warp per (b, p); lane covers 4 h.
// ---------------------------------------------------------------------------
__global__ __launch_bounds__(256) void combine_kernel(float* __restrict__ out)
{
    const int gw = (blockIdx.x * blockDim.x + threadIdx.x) >> 5;
    const int lane = threadIdx.x & 31;
    if (gw >= NB * NN) return;
    const int b = gw >> 13;
    const int p = gw & (NN - 1);

    size_t rows[4];
    float dens[4];
    int cnt = 0;
    float dsum = 0.f;
    #pragma unroll
    for (int i = 0; i < 4; i++) {
        if ((p & ((1 << i) - 1)) == 0) {
            int s = p >> (10 + i);
            int j = (p & ((1024 << i) - 1)) >> i;
            int cbase = 16384 - (16384 >> i);
            size_t row = (size_t)b * TOTROWS + cbase + s * 1024 + j;
            float d = g_d[row];
            rows[cnt] = row;
            dens[cnt] = d;
            dsum += d;
            cnt++;
        }
    }

    const int c = lane * 4;
    float4 acc = make_float4(0.f, 0.f, 0.f, 0.f);
    for (int q = 0; q < cnt; q++) {
        float wgt = dens[q] / dsum;
        float4 ov = *(const float4*)&g_o[rows[q] * NH + c];
        acc.x += ov.x * wgt;
        acc.y += ov.y * wgt;
        acc.z += ov.z * wgt;
        acc.w += ov.w * wgt;
    }
    *(float4*)&out[((size_t)b * NN + p) * NH + c] = acc;
}

// ---------------------------------------------------------------------------
extern "C" void kernel_launch(void* const* d_in, const int* in_sizes, int n_in,
                              void* d_out, int out_size)
{
    const float* x  = (const float*)d_in[0];
    const float* Wq = (const float*)d_in[1];
    const float* Wk = (const float*)d_in[2];
    const float* Wv = (const float*)d_in[3];
    float* out = (float*)d_out;

    cudaFuncSetAttribute((const void*)proj_mma,
                         cudaFuncAttributeMaxDynamicSharedMemorySize, PROJ_SMEM_BYTES);
    cudaFuncSetAttribute((const void*)attn_mma,
                         cudaFuncAttributeMaxDynamicSharedMemorySize, ATTN_SMEM_BYTES);

    split_w<<<dim3(32, 4, 3), dim3(32, 8)>>>(Wq, Wk, Wv);
    proj_mma<<<dim3(256, 3), 256, PROJ_SMEM_BYTES>>>(x);
    attn_mma<<<480, 256, ATTN_SMEM_BYTES>>>();
    combine_kernel<<<(NB * NN * 32 + 255) / 256, 256>>>(out);
}

// round 6
// speedup vs baseline: 3.0284x; 1.0913x over previous
#include <cuda_runtime.h>
#include <cuda_fp16.h>
#include <math.h>
#include <stdint.h>

// Problem constants
#define NB 4
#define NN 8192
#define NC 1024
#define NH 128
#define TOTROWS 15360   // 8192 + 4096 + 2048 + 1024 scratch rows per batch

// Scratch (device globals)
__device__ __half g_qh[NB * NN * NH], g_ql[NB * NN * NH];
__device__ __half g_kh[NB * NN * NH], g_kl[NB * NN * NH];
__device__ __half g_vh[NB * NN * NH], g_vl[NB * NN * NH];
__device__ __half g_wth[3 * 128 * 1024], g_wtl[3 * 128 * 1024]; // W^T hi/lo [w][n][k]
__device__ float g_o[(size_t)NB * TOTROWS * NH];
__device__ float g_d[NB * TOTROWS];

// ============================ helpers ============================
__device__ __forceinline__ uint32_t smem_u32(const void* p) {
    uint32_t a;
    asm("{ .reg .u64 t; cvta.to.shared.u64 t, %1; cvt.u32.u64 %0, t; }"
        : "=r"(a) : "l"(p));
    return a;
}

__device__ __forceinline__ void ldsm_x4(uint32_t r[4], uint32_t addr) {
    asm volatile("ldmatrix.sync.aligned.m8n8.x4.shared.b16 {%0,%1,%2,%3}, [%4];"
                 : "=r"(r[0]), "=r"(r[1]), "=r"(r[2]), "=r"(r[3]) : "r"(addr));
}
__device__ __forceinline__ void ldsm_x4_t(uint32_t r[4], uint32_t addr) {
    asm volatile("ldmatrix.sync.aligned.m8n8.x4.trans.shared.b16 {%0,%1,%2,%3}, [%4];"
                 : "=r"(r[0]), "=r"(r[1]), "=r"(r[2]), "=r"(r[3]) : "r"(addr));
}

// D(+=) A@B : m16n8k16 fp16 -> f32
__device__ __forceinline__ void mma16816(float c[4], const uint32_t a[4],
                                         uint32_t b0, uint32_t b1) {
    asm volatile(
        "mma.sync.aligned.m16n8k16.row.col.f32.f16.f16.f32 "
        "{%0,%1,%2,%3}, {%4,%5,%6,%7}, {%8,%9}, {%0,%1,%2,%3};"
        : "+f"(c[0]), "+f"(c[1]), "+f"(c[2]), "+f"(c[3])
        : "r"(a[0]), "r"(a[1]), "r"(a[2]), "r"(a[3]), "r"(b0), "r"(b1));
}

// split two fp32 into packed fp16x2 hi and lo (x = hi + lo + O(2^-22))
__device__ __forceinline__ void split2(float x, float y, uint32_t& hi, uint32_t& lo) {
    __half hx = __float2half_rn(x);
    __half hy = __float2half_rn(y);
    __half lx = __float2half_rn(x - __half2float(hx));
    __half ly = __float2half_rn(y - __half2float(hy));
    __half2 h2 = __halves2half2(hx, hy);
    __half2 l2 = __halves2half2(lx, ly);
    hi = *(uint32_t*)&h2;
    lo = *(uint32_t*)&l2;
}

// pack two f32 (even col -> lo, odd col -> hi) into fp16x2
__device__ __forceinline__ uint32_t pack_f16x2(float even, float odd) {
    uint32_t d;
    asm("cvt.rn.f16x2.f32 %0, %1, %2;" : "=r"(d) : "f"(odd), "f"(even));
    return d;
}
// packed fp16x2 exp2
__device__ __forceinline__ uint32_t ex2_f16x2(uint32_t a) {
    uint32_t d;
    asm("ex2.approx.f16x2 %0, %1;" : "=r"(d) : "r"(a));
    return d;
}
__device__ __forceinline__ float ex2f(float x) {
    float r;
    asm("ex2.approx.f32 %0, %1;" : "=f"(r) : "f"(x));
    return r;
}

// cp.async helpers
__device__ __forceinline__ void cp16(uint32_t dst, const void* src) {
    asm volatile("cp.async.cg.shared.global [%0], [%1], 16;" :: "r"(dst), "l"(src));
}
__device__ __forceinline__ void cp_commit() {
    asm volatile("cp.async.commit_group;" ::: "memory");
}
template <int N>
__device__ __forceinline__ void cp_wait() {
    asm volatile("cp.async.wait_group %0;" :: "n"(N) : "memory");
}

// ---------------------------------------------------------------------------
// Kernel 0: transpose + split W -> g_wth/g_wtl [w][n=128][k=1024] fp16
// ---------------------------------------------------------------------------
__global__ __launch_bounds__(256) void split_w(
    const float* __restrict__ Wq, const float* __restrict__ Wk,
    const float* __restrict__ Wv)
{
    __shared__ float tile[32][33];
    const float* W = (blockIdx.z == 0) ? Wq : (blockIdx.z == 1) ? Wk : Wv;
    const int k0 = blockIdx.x * 32;
    const int n0 = blockIdx.y * 32;
    const int tx = threadIdx.x, ty = threadIdx.y;
    #pragma unroll
    for (int i = ty; i < 32; i += 8)
        tile[i][tx] = W[(size_t)(k0 + i) * NH + n0 + tx];
    __syncthreads();
    #pragma unroll
    for (int i = ty; i < 32; i += 8) {
        float v = tile[tx][i];
        __half h = __float2half_rn(v);
        __half l = __float2half_rn(v - __half2float(h));
        size_t idx = (size_t)blockIdx.z * 131072 + (size_t)(n0 + i) * 1024 + k0 + tx;
        g_wth[idx] = h;
        g_wtl[idx] = l;
    }
}

// ---------------------------------------------------------------------------
// Kernel 1: QKV projection, fp16x3 mma.sync. (structure unchanged from R5)
// ---------------------------------------------------------------------------
#define PSTR 40                 // padded k stride (fp16 elements)
#define PBUF (128 * PSTR)       // elements per smem array
#define PROJ_SMEM_BYTES (2 * 4 * PBUF * 2)   // 2 buffers x 4 arrays

__global__ __launch_bounds__(256) void proj_mma(const float* __restrict__ x)
{
    extern __shared__ __half psm[];
    const int t = threadIdx.x;
    const int lane = t & 31;
    const int wid = t >> 5;
    const int wm = wid & 1;
    const int wn = wid >> 1;
    const size_t m0 = (size_t)blockIdx.x * 128;
    const int wsel = blockIdx.y;
    const __half* wth = g_wth + (size_t)wsel * 131072;
    const __half* wtl = g_wtl + (size_t)wsel * 131072;

    float acc[4][4][4];
    #pragma unroll
    for (int i = 0; i < 4; i++)
        #pragma unroll
        for (int j = 0; j < 4; j++)
            #pragma unroll
            for (int e = 0; e < 4; e++) acc[i][j][e] = 0.f;

    float4 sa[4];
    uint4 sbh[2], sbl[2];

    const int a_row[4] = { t >> 3, (t + 256) >> 3, (t + 512) >> 3, (t + 768) >> 3 };
    const int a_c4 = (t & 7) * 4;

    auto load_stage = [&](int k0) {
        #pragma unroll
        for (int p = 0; p < 4; p++)
            sa[p] = *(const float4*)&x[(m0 + a_row[p]) * NC + k0 + a_c4];
        #pragma unroll
        for (int p = 0; p < 2; p++) {
            int idx = t + p * 256;
            int row = idx >> 2, c8 = idx & 3;
            sbh[p] = *(const uint4*)&wth[(size_t)row * 1024 + k0 + c8 * 8];
            sbl[p] = *(const uint4*)&wtl[(size_t)row * 1024 + k0 + c8 * 8];
        }
    };
    auto store_stage = [&](int buf) {
        __half* AH = psm + buf * 4 * PBUF;
        __half* AL = AH + PBUF;
        __half* BH = AH + 2 * PBUF;
        __half* BL = AH + 3 * PBUF;
        #pragma unroll
        for (int p = 0; p < 4; p++) {
            uint32_t h01, l01, h23, l23;
            split2(sa[p].x, sa[p].y, h01, l01);
            split2(sa[p].z, sa[p].w, h23, l23);
            uint32_t off = a_row[p] * PSTR + a_c4;
            *(uint2*)&AH[off] = make_uint2(h01, h23);
            *(uint2*)&AL[off] = make_uint2(l01, l23);
        }
        #pragma unroll
        for (int p = 0; p < 2; p++) {
            int idx = t + p * 256;
            int row = idx >> 2, c8 = idx & 3;
            *(uint4*)&BH[row * PSTR + c8 * 8] = sbh[p];
            *(uint4*)&BL[row * PSTR + c8 * 8] = sbl[p];
        }
    };

    const uint32_t smbase = smem_u32(psm);
    const int lr = lane & 15;
    const int lc = (lane >> 4) * 8;

    auto compute = [&](int buf) {
        const uint32_t AHb = smbase + (buf * 4 * PBUF) * 2;
        const uint32_t ALb = AHb + PBUF * 2;
        const uint32_t BHb = AHb + 2 * PBUF * 2;
        const uint32_t BLb = AHb + 3 * PBUF * 2;
        #pragma unroll
        for (int ks = 0; ks < 2; ks++) {
            uint32_t ah[4][4], al[4][4];
            #pragma unroll
            for (int i = 0; i < 4; i++) {
                uint32_t off = ((wm * 64 + i * 16 + lr) * PSTR + ks * 16 + lc) * 2;
                ldsm_x4(ah[i], AHb + off);
                ldsm_x4(al[i], ALb + off);
            }
            #pragma unroll
            for (int jj = 0; jj < 2; jj++) {
                uint32_t off = ((wn * 32 + jj * 16 + lr) * PSTR + ks * 16 + lc) * 2;
                uint32_t bh[4], bl[4];
                ldsm_x4(bh, BHb + off);
                ldsm_x4(bl, BLb + off);
                #pragma unroll
                for (int i = 0; i < 4; i++) {
                    mma16816(acc[i][2 * jj],     ah[i], bh[0], bh[2]);
                    mma16816(acc[i][2 * jj],     al[i], bh[0], bh[2]);
                    mma16816(acc[i][2 * jj],     ah[i], bl[0], bl[2]);
                    mma16816(acc[i][2 * jj + 1], ah[i], bh[1], bh[3]);
                    mma16816(acc[i][2 * jj + 1], al[i], bh[1], bh[3]);
                    mma16816(acc[i][2 * jj + 1], ah[i], bl[1], bl[3]);
                }
            }
        }
    };

    load_stage(0);
    for (int c = 0; c < 32; c++) {
        store_stage(c & 1);
        __syncthreads();
        if (c + 1 < 32) load_stage((c + 1) * 32);
        compute(c & 1);
    }

    // epilogue: q pre-scaled by log2(e)/sqrt(128) -> attention works in log2 domain
    const float scale = (wsel == 0) ? (0.08838834764831843f * 1.4426950408889634f) : 1.0f;
    __half* DH = (wsel == 0) ? g_qh : (wsel == 1) ? g_kh : g_vh;
    __half* DL = (wsel == 0) ? g_ql : (wsel == 1) ? g_kl : g_vl;
    #pragma unroll
    for (int i = 0; i < 4; i++) {
        #pragma unroll
        for (int j = 0; j < 4; j++) {
            const int col = wn * 32 + j * 8 + 2 * (lane & 3);
            #pragma unroll
            for (int z = 0; z < 2; z++) {
                const size_t row = m0 + wm * 64 + i * 16 + (lane >> 2) + 8 * z;
                uint32_t hi, lo;
                split2(acc[i][j][2 * z] * scale, acc[i][j][2 * z + 1] * scale, hi, lo);
                *(uint32_t*)&DH[row * NH + col] = hi;
                *(uint32_t*)&DL[row * NH + col] = lo;
            }
        }
    }
}

// ---------------------------------------------------------------------------
// Kernel 2: causal flash attention, fp16 mma.sync, packed-fp16 exp2 softmax.
// 128-row Q tiles, 8 warps, cp.async double-buffered K/V.
// V carries 8 constant ones-columns (cols 128..135) -> row-sums via MMA.
// ---------------------------------------------------------------------------
#define ASTR 136                        // Q/K padded stride (fp16 elems)
#define VSTR 152                        // V padded stride (128 data + 16 ones/pad)
#define QTILE (128 * ASTR)              // 17408
#define KTILE (64 * ASTR)               // 8704
#define VTILE (64 * VSTR)               // 9728
#define BUFSZ (2 * KTILE + 2 * VTILE)   // 36864 elems per buffer
#define ATTN_SMEM_BYTES ((2 * QTILE + 2 * BUFSZ) * 2)   // 217088 B

__global__ __launch_bounds__(256) void attn_mma()
{
    extern __shared__ __half asm_[];
    const int blk = blockIdx.x;
    const int qb  = 7 - blk / 60;       // heavy tiles first
    const int t2  = blk % 60;
    const int b   = t2 / 15;
    const int cs  = t2 % 15;
    int cfg, seg;
    if (cs < 8)       { cfg = 0; seg = cs; }
    else if (cs < 12) { cfg = 1; seg = cs - 8; }
    else if (cs < 14) { cfg = 2; seg = cs - 12; }
    else              { cfg = 3; seg = 0; }
    const int rr = 1 << cfg;
    const int ww = 1024 << cfg;

    const int t = threadIdx.x;
    const int lane = t & 31;
    const int w = t >> 5;
    const size_t tok0 = (size_t)b * NN + seg * ww;

    const uint32_t sb = smem_u32(asm_);
    const uint32_t QHb = sb;
    const uint32_t QLb = sb + QTILE * 2;

    // element offsets of per-buffer arrays
    auto kh_off = [](int buf) { return 2 * QTILE + buf * BUFSZ; };
    auto kl_off = [](int buf) { return 2 * QTILE + buf * BUFSZ + KTILE; };
    auto vh_off = [](int buf) { return 2 * QTILE + buf * BUFSZ + 2 * KTILE; };
    auto vl_off = [](int buf) { return 2 * QTILE + buf * BUFSZ + 2 * KTILE + VTILE; };

    // ---- constant ones-columns in VH (cols 128..135 = 1, 136..143 = 0) ----
    for (int i = t; i < 2 * 64 * 16; i += 256) {
        int buf = i >> 10;
        int r = (i & 1023) >> 4;
        int c = i & 15;
        asm_[vh_off(buf) + r * VSTR + 128 + c] = (c < 8) ? __float2half(1.0f)
                                                         : __float2half(0.0f);
    }

    // ---- issue Q tile fill (hi/lo) via cp.async : part of group 0 ----
    #pragma unroll
    for (int i = 0; i < 8; i++) {
        int idx = t + i * 256;
        int row = idx >> 4;
        int c = idx & 15;
        size_t src = (tok0 + (size_t)(qb * 128 + row) * rr) * NH + c * 8;
        uint32_t d = (row * ASTR + c * 8) * 2;
        cp16(QHb + d, g_qh + src);
        cp16(QLb + d, g_ql + src);
    }

    auto issue_kv = [&](int kt, int buf) {
        #pragma unroll
        for (int i = 0; i < 4; i++) {
            int idx = t + i * 256;
            int row = idx >> 4;
            int c = idx & 15;
            size_t src = (tok0 + (size_t)(kt * 64 + row) * rr) * NH + c * 8;
            cp16(sb + (kh_off(buf) + row * ASTR + c * 8) * 2, g_kh + src);
            cp16(sb + (kl_off(buf) + row * ASTR + c * 8) * 2, g_kl + src);
            cp16(sb + (vh_off(buf) + row * VSTR + c * 8) * 2, g_vh + src);
            cp16(sb + (vl_off(buf) + row * VSTR + c * 8) * 2, g_vl + src);
        }
    };

    const int L = 2 * qb + 1;
    issue_kv(0, 0);
    cp_commit();
    issue_kv(1, 1);
    cp_commit();

    float o[16][4];
    float osum[4] = {0.f, 0.f, 0.f, 0.f};   // l accumulator (ones-column MMA)
    #pragma unroll
    for (int j = 0; j < 16; j++)
        #pragma unroll
        for (int e = 0; e < 4; e++) o[j][e] = 0.f;
    float m_i[2] = { -INFINITY, -INFINITY };

    const int lr = lane & 15;
    const int lc = (lane >> 4) * 8;

    for (int kt = 0; kt <= L; kt++) {
        if (kt < L) cp_wait<1>(); else cp_wait<0>();
        __syncthreads();

        const int buf = kt & 1;
        const uint32_t KHb = sb + kh_off(buf) * 2;
        const uint32_t KLb = sb + kl_off(buf) * 2;
        const uint32_t VHb = sb + vh_off(buf) * 2;
        const uint32_t VLb = sb + vl_off(buf) * 2;

        const bool active = (qb * 128 + w * 16 + 15) >= kt * 64;
        if (active) {
            // ---- S = Q @ K^T (log2 domain; 3-term fp16) ----
            float s[8][4];
            #pragma unroll
            for (int j = 0; j < 8; j++)
                #pragma unroll
                for (int e = 0; e < 4; e++) s[j][e] = 0.f;

            #pragma unroll
            for (int ks = 0; ks < 8; ks++) {
                uint32_t qh[4], ql[4];
                {
                    uint32_t off = ((w * 16 + lr) * ASTR + ks * 16 + lc) * 2;
                    ldsm_x4(qh, QHb + off);
                    ldsm_x4(ql, QLb + off);
                }
                #pragma unroll
                for (int jj = 0; jj < 4; jj++) {
                    uint32_t off = ((jj * 16 + lr) * ASTR + ks * 16 + lc) * 2;
                    uint32_t kh[4], kl[4];
                    ldsm_x4(kh, KHb + off);
                    ldsm_x4(kl, KLb + off);
                    mma16816(s[2 * jj],     qh, kh[0], kh[2]);
                    mma16816(s[2 * jj],     ql, kh[0], kh[2]);
                    mma16816(s[2 * jj],     qh, kl[0], kl[2]);
                    mma16816(s[2 * jj + 1], qh, kh[1], kh[3]);
                    mma16816(s[2 * jj + 1], ql, kh[1], kh[3]);
                    mma16816(s[2 * jj + 1], qh, kl[1], kl[3]);
                }
            }

            // ---- causal mask ----
            if (kt >= 2 * qb) {
                #pragma unroll
                for (int j = 0; j < 8; j++)
                    #pragma unroll
                    for (int z = 0; z < 2; z++) {
                        int gq = qb * 128 + w * 16 + (lane >> 2) + 8 * z;
                        int gk = kt * 64 + j * 8 + 2 * (lane & 3);
                        if (gk > gq)     s[j][2 * z]     = -INFINITY;
                        if (gk + 1 > gq) s[j][2 * z + 1] = -INFINITY;
                    }
            }

            // ---- online softmax: max + rescale (exp2 domain) ----
            float mn[2];
            #pragma unroll
            for (int z = 0; z < 2; z++) {
                float mx = -INFINITY;
                #pragma unroll
                for (int j = 0; j < 8; j++)
                    mx = fmaxf(mx, fmaxf(s[j][2 * z], s[j][2 * z + 1]));
                mx = fmaxf(mx, __shfl_xor_sync(0xffffffffu, mx, 1));
                mx = fmaxf(mx, __shfl_xor_sync(0xffffffffu, mx, 2));
                mn[z] = fmaxf(m_i[z], mx);
                float sc = ex2f(m_i[z] - mn[z]);
                m_i[z] = mn[z];
                #pragma unroll
                for (int j = 0; j < 16; j++) {
                    o[j][2 * z] *= sc;
                    o[j][2 * z + 1] *= sc;
                }
                osum[2 * z] *= sc;
                osum[2 * z + 1] *= sc;
            }

            // ---- P = exp2(S - m) packed fp16x2 (one MUFU per 2 elems) ----
            uint32_t p16[8][2];
            #pragma unroll
            for (int j = 0; j < 8; j++) {
                p16[j][0] = ex2_f16x2(pack_f16x2(s[j][0] - mn[0], s[j][1] - mn[0]));
                p16[j][1] = ex2_f16x2(pack_f16x2(s[j][2] - mn[1], s[j][3] - mn[1]));
            }

            // ---- O += P @ V (P exact fp16 -> 2 terms) + ones-column row sums ----
            #pragma unroll
            for (int kk = 0; kk < 4; kk++) {
                const uint32_t a[4] = { p16[2 * kk][0], p16[2 * kk][1],
                                        p16[2 * kk + 1][0], p16[2 * kk + 1][1] };
                #pragma unroll
                for (int jj = 0; jj < 8; jj++) {
                    uint32_t off = ((kk * 16 + lr) * VSTR + jj * 16 + lc) * 2;
                    uint32_t vh[4], vl[4];
                    ldsm_x4_t(vh, VHb + off);
                    ldsm_x4_t(vl, VLb + off);
                    mma16816(o[2 * jj],     a, vh[0], vh[1]);
                    mma16816(o[2 * jj],     a, vl[0], vl[1]);
                    mma16816(o[2 * jj + 1], a, vh[2], vh[3]);
                    mma16816(o[2 * jj + 1], a, vl[2], vl[3]);
                }
                // row sums via ones columns (128..135)
                uint32_t vs[4];
                ldsm_x4_t(vs, VHb + ((kk * 16 + lr) * VSTR + 128 + lc) * 2);
                mma16816(osum, a, vs[0], vs[1]);
            }
        }

        __syncthreads();
        if (kt + 2 <= L) {
            issue_kv(kt + 2, kt & 1);
            cp_commit();
        }
    }

    // ---- epilogue: normalize, write o and denom = l * 2^m ----
    const int cbase = 16384 - (16384 >> cfg);
    const size_t obase = (size_t)b * TOTROWS + cbase + seg * 1024 + qb * 128;
    #pragma unroll
    for (int z = 0; z < 2; z++) {
        const size_t row = obase + w * 16 + (lane >> 2) + 8 * z;
        const float l = osum[2 * z];
        const float inv = 1.0f / l;
        #pragma unroll
        for (int j = 0; j < 16; j++) {
            const int col = j * 8 + 2 * (lane & 3);
            *(float2*)&g_o[row * NH + col] =
                make_float2(o[j][2 * z] * inv, o[j][2 * z + 1] * inv);
        }
        if ((lane & 3) == 0)
            g_d[row] = l * exp2f(m_i[z]);
    }
}

// ---------------------------------------------------------------------------
// Kernel 3: cross-config combine. One warp per (b, p); lane covers 4 h.
// ---------------------------------------------------------------------------
__global__ __launch_bounds__(256) void combine_kernel(float* __restrict__ out)
{
    const int gw = (blockIdx.x * blockDim.x + threadIdx.x) >> 5;
    const int lane = threadIdx.x & 31;
    if (gw >= NB * NN) return;
    const int b = gw >> 13;
    const int p = gw & (NN - 1);

    size_t rows[4];
    float dens[4];
    int cnt = 0;
    float dsum = 0.f;
    #pragma unroll
    for (int i = 0; i < 4; i++) {
        if ((p & ((1 << i) - 1)) == 0) {
            int s = p >> (10 + i);
            int j = (p & ((1024 << i) - 1)) >> i;
            int cbase = 16384 - (16384 >> i);
            size_t row = (size_t)b * TOTROWS + cbase + s * 1024 + j;
            float d = g_d[row];
            rows[cnt] = row;
            dens[cnt] = d;
            dsum += d;
            cnt++;
        }
    }

    const int c = lane * 4;
    float4 acc = make_float4(0.f, 0.f, 0.f, 0.f);
    for (int q = 0; q < cnt; q++) {
        float wgt = dens[q] / dsum;
        float4 ov = *(const float4*)&g_o[rows[q] * NH + c];
        acc.x += ov.x * wgt;
        acc.y += ov.y * wgt;
        acc.z += ov.z * wgt;
        acc.w += ov.w * wgt;
    }
    *(float4*)&out[((size_t)b * NN + p) * NH + c] = acc;
}

// ---------------------------------------------------------------------------
extern "C" void kernel_launch(void* const* d_in, const int* in_sizes, int n_in,
                              void* d_out, int out_size)
{
    const float* x  = (const float*)d_in[0];
    const float* Wq = (const float*)d_in[1];
    const float* Wk = (const float*)d_in[2];
    const float* Wv = (const float*)d_in[3];
    float* out = (float*)d_out;

    cudaFuncSetAttribute((const void*)proj_mma,
                         cudaFuncAttributeMaxDynamicSharedMemorySize, PROJ_SMEM_BYTES);
    cudaFuncSetAttribute((const void*)attn_mma,
                         cudaFuncAttributeMaxDynamicSharedMemorySize, ATTN_SMEM_BYTES);

    split_w<<<dim3(32, 4, 3), dim3(32, 8)>>>(Wq, Wk, Wv);
    proj_mma<<<dim3(256, 3), 256, PROJ_SMEM_BYTES>>>(x);
    attn_mma<<<480, 256, ATTN_SMEM_BYTES>>>();
    combine_kernel<<<(NB * NN * 32 + 255) / 256, 256>>>(out);
}

// round 7
// speedup vs baseline: 3.8894x; 1.2843x over previous
#include <cuda_runtime.h>
#include <cuda_fp16.h>
#include <math.h>
#include <stdint.h>

// Problem constants
#define NB 4
#define NN 8192
#define NC 1024
#define NH 128
#define TOTROWS 15360   // 8192 + 4096 + 2048 + 1024 scratch rows per batch

// Scratch (device globals)
__device__ __half g_qh[NB * NN * NH], g_ql[NB * NN * NH];
__device__ __half g_kh[NB * NN * NH];
__device__ __half g_vh[NB * NN * NH], g_vl[NB * NN * NH];
__device__ __half g_wth[3 * 128 * 1024];   // W^T hi [w][n][k] (lo dropped: 2-term proj)
__device__ float g_o[(size_t)NB * TOTROWS * NH];
__device__ float g_d[NB * TOTROWS];

// ============================ helpers ============================
__device__ __forceinline__ uint32_t smem_u32(const void* p) {
    uint32_t a;
    asm("{ .reg .u64 t; cvta.to.shared.u64 t, %1; cvt.u32.u64 %0, t; }"
        : "=r"(a) : "l"(p));
    return a;
}

__device__ __forceinline__ void ldsm_x4(uint32_t r[4], uint32_t addr) {
    asm volatile("ldmatrix.sync.aligned.m8n8.x4.shared.b16 {%0,%1,%2,%3}, [%4];"
                 : "=r"(r[0]), "=r"(r[1]), "=r"(r[2]), "=r"(r[3]) : "r"(addr));
}
__device__ __forceinline__ void ldsm_x4_t(uint32_t r[4], uint32_t addr) {
    asm volatile("ldmatrix.sync.aligned.m8n8.x4.trans.shared.b16 {%0,%1,%2,%3}, [%4];"
                 : "=r"(r[0]), "=r"(r[1]), "=r"(r[2]), "=r"(r[3]) : "r"(addr));
}

// D(+=) A@B : m16n8k16 fp16 -> f32
__device__ __forceinline__ void mma16816(float c[4], const uint32_t a[4],
                                         uint32_t b0, uint32_t b1) {
    asm volatile(
        "mma.sync.aligned.m16n8k16.row.col.f32.f16.f16.f32 "
        "{%0,%1,%2,%3}, {%4,%5,%6,%7}, {%8,%9}, {%0,%1,%2,%3};"
        : "+f"(c[0]), "+f"(c[1]), "+f"(c[2]), "+f"(c[3])
        : "r"(a[0]), "r"(a[1]), "r"(a[2]), "r"(a[3]), "r"(b0), "r"(b1));
}

// split two fp32 into packed fp16x2 hi and lo
__device__ __forceinline__ void split2(float x, float y, uint32_t& hi, uint32_t& lo) {
    __half hx = __float2half_rn(x);
    __half hy = __float2half_rn(y);
    __half lx = __float2half_rn(x - __half2float(hx));
    __half ly = __float2half_rn(y - __half2float(hy));
    __half2 h2 = __halves2half2(hx, hy);
    __half2 l2 = __halves2half2(lx, ly);
    hi = *(uint32_t*)&h2;
    lo = *(uint32_t*)&l2;
}

__device__ __forceinline__ uint32_t pack_f16x2(float even, float odd) {
    uint32_t d;
    asm("cvt.rn.f16x2.f32 %0, %1, %2;" : "=r"(d) : "f"(odd), "f"(even));
    return d;
}
__device__ __forceinline__ uint32_t ex2_f16x2(uint32_t a) {
    uint32_t d;
    asm("ex2.approx.f16x2 %0, %1;" : "=r"(d) : "r"(a));
    return d;
}
__device__ __forceinline__ float ex2f(float x) {
    float r;
    asm("ex2.approx.f32 %0, %1;" : "=f"(r) : "f"(x));
    return r;
}

// cp.async helpers
__device__ __forceinline__ void cp16(uint32_t dst, const void* src) {
    asm volatile("cp.async.cg.shared.global [%0], [%1], 16;" :: "r"(dst), "l"(src));
}
__device__ __forceinline__ void cp_commit() {
    asm volatile("cp.async.commit_group;" ::: "memory");
}
template <int N>
__device__ __forceinline__ void cp_wait() {
    asm volatile("cp.async.wait_group %0;" :: "n"(N) : "memory");
}

// ---------------------------------------------------------------------------
// Kernel 0: transpose W (hi only) -> g_wth [w][n=128][k=1024] fp16
// ---------------------------------------------------------------------------
__global__ __launch_bounds__(256) void split_w(
    const float* __restrict__ Wq, const float* __restrict__ Wk,
    const float* __restrict__ Wv)
{
    __shared__ float tile[32][33];
    const float* W = (blockIdx.z == 0) ? Wq : (blockIdx.z == 1) ? Wk : Wv;
    const int k0 = blockIdx.x * 32;
    const int n0 = blockIdx.y * 32;
    const int tx = threadIdx.x, ty = threadIdx.y;
    #pragma unroll
    for (int i = ty; i < 32; i += 8)
        tile[i][tx] = W[(size_t)(k0 + i) * NH + n0 + tx];
    __syncthreads();
    #pragma unroll
    for (int i = ty; i < 32; i += 8) {
        size_t idx = (size_t)blockIdx.z * 131072 + (size_t)(n0 + i) * 1024 + k0 + tx;
        g_wth[idx] = __float2half_rn(tile[tx][i]);
    }
}

// ---------------------------------------------------------------------------
// Kernel 1: QKV projection, 2-term fp16 mma.sync: D = (xh + xl) @ Wh
// CTA tile M=128, N=128, K chunks of 32. grid=(256,3) y->Wq/Wk/Wv.
// smem per buffer: AH, AL, BH (Bl dropped).
// ---------------------------------------------------------------------------
#define PSTR 40                 // padded k stride (fp16 elements)
#define PBUF (128 * PSTR)       // elements per smem array
#define PROJ_SMEM_BYTES (2 * 3 * PBUF * 2)   // 2 buffers x 3 arrays

__global__ __launch_bounds__(256) void proj_mma(const float* __restrict__ x)
{
    extern __shared__ __half psm[];
    const int t = threadIdx.x;
    const int lane = t & 31;
    const int wid = t >> 5;
    const int wm = wid & 1;
    const int wn = wid >> 1;
    const size_t m0 = (size_t)blockIdx.x * 128;
    const int wsel = blockIdx.y;
    const __half* wth = g_wth + (size_t)wsel * 131072;

    float acc[4][4][4];
    #pragma unroll
    for (int i = 0; i < 4; i++)
        #pragma unroll
        for (int j = 0; j < 4; j++)
            #pragma unroll
            for (int e = 0; e < 4; e++) acc[i][j][e] = 0.f;

    float4 sa[4];
    uint4 sbh[2];

    const int a_row[4] = { t >> 3, (t + 256) >> 3, (t + 512) >> 3, (t + 768) >> 3 };
    const int a_c4 = (t & 7) * 4;

    auto load_stage = [&](int k0) {
        #pragma unroll
        for (int p = 0; p < 4; p++)
            sa[p] = *(const float4*)&x[(m0 + a_row[p]) * NC + k0 + a_c4];
        #pragma unroll
        for (int p = 0; p < 2; p++) {
            int idx = t + p * 256;
            int row = idx >> 2, c8 = idx & 3;
            sbh[p] = *(const uint4*)&wth[(size_t)row * 1024 + k0 + c8 * 8];
        }
    };
    auto store_stage = [&](int buf) {
        __half* AH = psm + buf * 3 * PBUF;
        __half* AL = AH + PBUF;
        __half* BH = AH + 2 * PBUF;
        #pragma unroll
        for (int p = 0; p < 4; p++) {
            uint32_t h01, l01, h23, l23;
            split2(sa[p].x, sa[p].y, h01, l01);
            split2(sa[p].z, sa[p].w, h23, l23);
            uint32_t off = a_row[p] * PSTR + a_c4;
            *(uint2*)&AH[off] = make_uint2(h01, h23);
            *(uint2*)&AL[off] = make_uint2(l01, l23);
        }
        #pragma unroll
        for (int p = 0; p < 2; p++) {
            int idx = t + p * 256;
            int row = idx >> 2, c8 = idx & 3;
            *(uint4*)&BH[row * PSTR + c8 * 8] = sbh[p];
        }
    };

    const uint32_t smbase = smem_u32(psm);
    const int lr = lane & 15;
    const int lc = (lane >> 4) * 8;

    auto compute = [&](int buf) {
        const uint32_t AHb = smbase + (buf * 3 * PBUF) * 2;
        const uint32_t ALb = AHb + PBUF * 2;
        const uint32_t BHb = AHb + 2 * PBUF * 2;
        #pragma unroll
        for (int ks = 0; ks < 2; ks++) {
            uint32_t ah[4][4], al[4][4];
            #pragma unroll
            for (int i = 0; i < 4; i++) {
                uint32_t off = ((wm * 64 + i * 16 + lr) * PSTR + ks * 16 + lc) * 2;
                ldsm_x4(ah[i], AHb + off);
                ldsm_x4(al[i], ALb + off);
            }
            #pragma unroll
            for (int jj = 0; jj < 2; jj++) {
                uint32_t off = ((wn * 32 + jj * 16 + lr) * PSTR + ks * 16 + lc) * 2;
                uint32_t bh[4];
                ldsm_x4(bh, BHb + off);
                #pragma unroll
                for (int i = 0; i < 4; i++) {
                    mma16816(acc[i][2 * jj],     ah[i], bh[0], bh[2]);
                    mma16816(acc[i][2 * jj],     al[i], bh[0], bh[2]);
                    mma16816(acc[i][2 * jj + 1], ah[i], bh[1], bh[3]);
                    mma16816(acc[i][2 * jj + 1], al[i], bh[1], bh[3]);
                }
            }
        }
    };

    load_stage(0);
    for (int c = 0; c < 32; c++) {
        store_stage(c & 1);
        __syncthreads();
        if (c + 1 < 32) load_stage((c + 1) * 32);
        compute(c & 1);
    }

    // epilogue: q pre-scaled by log2(e)/sqrt(128); K stores hi only.
    const float scale = (wsel == 0) ? (0.08838834764831843f * 1.4426950408889634f) : 1.0f;
    __half* DH = (wsel == 0) ? g_qh : (wsel == 1) ? g_kh : g_vh;
    __half* DL = (wsel == 0) ? g_ql : (wsel == 1) ? (__half*)nullptr : g_vl;
    #pragma unroll
    for (int i = 0; i < 4; i++) {
        #pragma unroll
        for (int j = 0; j < 4; j++) {
            const int col = wn * 32 + j * 8 + 2 * (lane & 3);
            #pragma unroll
            for (int z = 0; z < 2; z++) {
                const size_t row = m0 + wm * 64 + i * 16 + (lane >> 2) + 8 * z;
                uint32_t hi, lo;
                split2(acc[i][j][2 * z] * scale, acc[i][j][2 * z + 1] * scale, hi, lo);
                *(uint32_t*)&DH[row * NH + col] = hi;
                if (wsel != 1)
                    *(uint32_t*)&DL[row * NH + col] = lo;
            }
        }
    }
}

// ---------------------------------------------------------------------------
// Kernel 2: causal flash attention, fp16 mma.sync, packed-fp16 exp2 softmax.
// QK 2-term (S = (Qh+Ql)·Kh), PV 2-term (P exact fp16, V hi/lo).
// 128-row Q tiles, 8 warps, cp.async double-buffered K/V.
// V carries 8 constant ones-columns (cols 128..135) -> row-sums via MMA.
// ---------------------------------------------------------------------------
#define ASTR 136                        // Q/K padded stride (fp16 elems)
#define VSTR 152                        // V padded stride (128 data + 16 ones/pad)
#define QTILE (128 * ASTR)              // 17408
#define KTILE (64 * ASTR)               // 8704
#define VTILE (64 * VSTR)               // 9728
#define BUFSZ (KTILE + 2 * VTILE)       // 28160 elems per buffer
#define ATTN_SMEM_BYTES ((2 * QTILE + 2 * BUFSZ) * 2)   // 182272 B

__global__ __launch_bounds__(256) void attn_mma()
{
    extern __shared__ __half asm_[];
    const int blk = blockIdx.x;
    const int qb  = 7 - blk / 60;       // heavy tiles first
    const int t2  = blk % 60;
    const int b   = t2 / 15;
    const int cs  = t2 % 15;
    int cfg, seg;
    if (cs < 8)       { cfg = 0; seg = cs; }
    else if (cs < 12) { cfg = 1; seg = cs - 8; }
    else if (cs < 14) { cfg = 2; seg = cs - 12; }
    else              { cfg = 3; seg = 0; }
    const int rr = 1 << cfg;
    const int ww = 1024 << cfg;

    const int t = threadIdx.x;
    const int lane = t & 31;
    const int w = t >> 5;
    const size_t tok0 = (size_t)b * NN + seg * ww;

    const uint32_t sb = smem_u32(asm_);
    const uint32_t QHb = sb;
    const uint32_t QLb = sb + QTILE * 2;

    auto kh_off = [](int buf) { return 2 * QTILE + buf * BUFSZ; };
    auto vh_off = [](int buf) { return 2 * QTILE + buf * BUFSZ + KTILE; };
    auto vl_off = [](int buf) { return 2 * QTILE + buf * BUFSZ + KTILE + VTILE; };

    // ---- constant ones-columns in VH (cols 128..135 = 1, 136..143 = 0) ----
    for (int i = t; i < 2 * 64 * 16; i += 256) {
        int buf = i >> 10;
        int r = (i & 1023) >> 4;
        int c = i & 15;
        asm_[vh_off(buf) + r * VSTR + 128 + c] = (c < 8) ? __float2half(1.0f)
                                                         : __float2half(0.0f);
    }

    // ---- issue Q tile fill (hi/lo) via cp.async : part of group 0 ----
    #pragma unroll
    for (int i = 0; i < 8; i++) {
        int idx = t + i * 256;
        int row = idx >> 4;
        int c = idx & 15;
        size_t src = (tok0 + (size_t)(qb * 128 + row) * rr) * NH + c * 8;
        uint32_t d = (row * ASTR + c * 8) * 2;
        cp16(QHb + d, g_qh + src);
        cp16(QLb + d, g_ql + src);
    }

    auto issue_kv = [&](int kt, int buf) {
        #pragma unroll
        for (int i = 0; i < 4; i++) {
            int idx = t + i * 256;
            int row = idx >> 4;
            int c = idx & 15;
            size_t src = (tok0 + (size_t)(kt * 64 + row) * rr) * NH + c * 8;
            cp16(sb + (kh_off(buf) + row * ASTR + c * 8) * 2, g_kh + src);
            cp16(sb + (vh_off(buf) + row * VSTR + c * 8) * 2, g_vh + src);
            cp16(sb + (vl_off(buf) + row * VSTR + c * 8) * 2, g_vl + src);
        }
    };

    const int L = 2 * qb + 1;
    issue_kv(0, 0);
    cp_commit();
    issue_kv(1, 1);
    cp_commit();

    float o[16][4];
    float osum[4] = {0.f, 0.f, 0.f, 0.f};   // l accumulator (ones-column MMA)
    #pragma unroll
    for (int j = 0; j < 16; j++)
        #pragma unroll
        for (int e = 0; e < 4; e++) o[j][e] = 0.f;
    float m_i[2] = { -INFINITY, -INFINITY };

    const int lr = lane & 15;
    const int lc = (lane >> 4) * 8;

    for (int kt = 0; kt <= L; kt++) {
        if (kt < L) cp_wait<1>(); else cp_wait<0>();
        __syncthreads();

        const int buf = kt & 1;
        const uint32_t KHb = sb + kh_off(buf) * 2;
        const uint32_t VHb = sb + vh_off(buf) * 2;
        const uint32_t VLb = sb + vl_off(buf) * 2;

        const bool active = (qb * 128 + w * 16 + 15) >= kt * 64;
        if (active) {
            // ---- S = (Qh+Ql) @ Kh^T (log2 domain; 2-term) ----
            float s[8][4];
            #pragma unroll
            for (int j = 0; j < 8; j++)
                #pragma unroll
                for (int e = 0; e < 4; e++) s[j][e] = 0.f;

            #pragma unroll
            for (int ks = 0; ks < 8; ks++) {
                uint32_t qh[4], ql[4];
                {
                    uint32_t off = ((w * 16 + lr) * ASTR + ks * 16 + lc) * 2;
                    ldsm_x4(qh, QHb + off);
                    ldsm_x4(ql, QLb + off);
                }
                #pragma unroll
                for (int jj = 0; jj < 4; jj++) {
                    uint32_t off = ((jj * 16 + lr) * ASTR + ks * 16 + lc) * 2;
                    uint32_t kh[4];
                    ldsm_x4(kh, KHb + off);
                    mma16816(s[2 * jj],     qh, kh[0], kh[2]);
                    mma16816(s[2 * jj],     ql, kh[0], kh[2]);
                    mma16816(s[2 * jj + 1], qh, kh[1], kh[3]);
                    mma16816(s[2 * jj + 1], ql, kh[1], kh[3]);
                }
            }

            // ---- causal mask ----
            if (kt >= 2 * qb) {
                #pragma unroll
                for (int j = 0; j < 8; j++)
                    #pragma unroll
                    for (int z = 0; z < 2; z++) {
                        int gq = qb * 128 + w * 16 + (lane >> 2) + 8 * z;
                        int gk = kt * 64 + j * 8 + 2 * (lane & 3);
                        if (gk > gq)     s[j][2 * z]     = -INFINITY;
                        if (gk + 1 > gq) s[j][2 * z + 1] = -INFINITY;
                    }
            }

            // ---- online softmax: max + rescale (exp2 domain) ----
            float mn[2];
            #pragma unroll
            for (int z = 0; z < 2; z++) {
                float mx = -INFINITY;
                #pragma unroll
                for (int j = 0; j < 8; j++)
                    mx = fmaxf(mx, fmaxf(s[j][2 * z], s[j][2 * z + 1]));
                mx = fmaxf(mx, __shfl_xor_sync(0xffffffffu, mx, 1));
                mx = fmaxf(mx, __shfl_xor_sync(0xffffffffu, mx, 2));
                mn[z] = fmaxf(m_i[z], mx);
                float sc = ex2f(m_i[z] - mn[z]);
                m_i[z] = mn[z];
                #pragma unroll
                for (int j = 0; j < 16; j++) {
                    o[j][2 * z] *= sc;
                    o[j][2 * z + 1] *= sc;
                }
                osum[2 * z] *= sc;
                osum[2 * z + 1] *= sc;
            }

            // ---- P = exp2(S - m) packed fp16x2 ----
            uint32_t p16[8][2];
            #pragma unroll
            for (int j = 0; j < 8; j++) {
                p16[j][0] = ex2_f16x2(pack_f16x2(s[j][0] - mn[0], s[j][1] - mn[0]));
                p16[j][1] = ex2_f16x2(pack_f16x2(s[j][2] - mn[1], s[j][3] - mn[1]));
            }

            // ---- O += P @ V (2-term) + ones-column row sums ----
            #pragma unroll
            for (int kk = 0; kk < 4; kk++) {
                const uint32_t a[4] = { p16[2 * kk][0], p16[2 * kk][1],
                                        p16[2 * kk + 1][0], p16[2 * kk + 1][1] };
                #pragma unroll
                for (int jj = 0; jj < 8; jj++) {
                    uint32_t off = ((kk * 16 + lr) * VSTR + jj * 16 + lc) * 2;
                    uint32_t vh[4], vl[4];
                    ldsm_x4_t(vh, VHb + off);
                    ldsm_x4_t(vl, VLb + off);
                    mma16816(o[2 * jj],     a, vh[0], vh[1]);
                    mma16816(o[2 * jj],     a, vl[0], vl[1]);
                    mma16816(o[2 * jj + 1], a, vh[2], vh[3]);
                    mma16816(o[2 * jj + 1], a, vl[2], vl[3]);
                }
                uint32_t vs[4];
                ldsm_x4_t(vs, VHb + ((kk * 16 + lr) * VSTR + 128 + lc) * 2);
                mma16816(osum, a, vs[0], vs[1]);
            }
        }

        __syncthreads();
        if (kt + 2 <= L) {
            issue_kv(kt + 2, kt & 1);
            cp_commit();
        }
    }

    // ---- epilogue: normalize, write o and denom = l * 2^m ----
    const int cbase = 16384 - (16384 >> cfg);
    const size_t obase = (size_t)b * TOTROWS + cbase + seg * 1024 + qb * 128;
    #pragma unroll
    for (int z = 0; z < 2; z++) {
        const size_t row = obase + w * 16 + (lane >> 2) + 8 * z;
        const float l = osum[2 * z];
        const float inv = 1.0f / l;
        #pragma unroll
        for (int j = 0; j < 16; j++) {
            const int col = j * 8 + 2 * (lane & 3);
            *(float2*)&g_o[row * NH + col] =
                make_float2(o[j][2 * z] * inv, o[j][2 * z + 1] * inv);
        }
        if ((lane & 3) == 0)
            g_d[row] = l * exp2f(m_i[z]);
    }
}

// ---------------------------------------------------------------------------
// Kernel 3: cross-config combine. One warp per (b, p); lane covers 4 h.
// ---------------------------------------------------------------------------
__global__ __launch_bounds__(256) void combine_kernel(float* __restrict__ out)
{
    const int gw = (blockIdx.x * blockDim.x + threadIdx.x) >> 5;
    const int lane = threadIdx.x & 31;
    if (gw >= NB * NN) return;
    const int b = gw >> 13;
    const int p = gw & (NN - 1);

    size_t rows[4];
    float dens[4];
    int cnt = 0;
    float dsum = 0.f;
    #pragma unroll
    for (int i = 0; i < 4; i++) {
        if ((p & ((1 << i) - 1)) == 0) {
            int s = p >> (10 + i);
            int j = (p & ((1024 << i) - 1)) >> i;
            int cbase = 16384 - (16384 >> i);
            size_t row = (size_t)b * TOTROWS + cbase + s * 1024 + j;
            float d = g_d[row];
            rows[cnt] = row;
            dens[cnt] = d;
            dsum += d;
            cnt++;
        }
    }

    const int c = lane * 4;
    float4 acc = make_float4(0.f, 0.f, 0.f, 0.f);
    for (int q = 0; q < cnt; q++) {
        float wgt = dens[q] / dsum;
        float4 ov = *(const float4*)&g_o[rows[q] * NH + c];
        acc.x += ov.x * wgt;
        acc.y += ov.y * wgt;
        acc.z += ov.z * wgt;
        acc.w += ov.w * wgt;
    }
    *(float4*)&out[((size_t)b * NN + p) * NH + c] = acc;
}

// ---------------------------------------------------------------------------
extern "C" void kernel_launch(void* const* d_in, const int* in_sizes, int n_in,
                              void* d_out, int out_size)
{
    const float* x  = (const float*)d_in[0];
    const float* Wq = (const float*)d_in[1];
    const float* Wk = (const float*)d_in[2];
    const float* Wv = (const float*)d_in[3];
    float* out = (float*)d_out;

    cudaFuncSetAttribute((const void*)proj_mma,
                         cudaFuncAttributeMaxDynamicSharedMemorySize, PROJ_SMEM_BYTES);
    cudaFuncSetAttribute((const void*)attn_mma,
                         cudaFuncAttributeMaxDynamicSharedMemorySize, ATTN_SMEM_BYTES);

    split_w<<<dim3(32, 4, 3), dim3(32, 8)>>>(Wq, Wk, Wv);
    proj_mma<<<dim3(256, 3), 256, PROJ_SMEM_BYTES>>>(x);
    attn_mma<<<480, 256, ATTN_SMEM_BYTES>>>();
    combine_kernel<<<(NB * NN * 32 + 255) / 256, 256>>>(out);
}

// round 8
// speedup vs baseline: 5.9183x; 1.5217x over previous
#include <cuda_runtime.h>
#include <cuda_fp16.h>
#include <math.h>
#include <stdint.h>

// Problem constants
#define NB 4
#define NN 8192
#define NC 1024
#define NH 128
#define TOTROWS 15360   // 8192 + 4096 + 2048 + 1024 scratch rows per batch

// Scratch (device globals)
__device__ __half g_qh[NB * NN * NH], g_ql[NB * NN * NH];
__device__ __half g_kh[NB * NN * NH];
__device__ __half g_vh[NB * NN * NH];
__device__ __half g_wth[3 * 128 * 1024];   // W^T hi [w][n][k]
__device__ float g_o[(size_t)NB * TOTROWS * NH];
__device__ float g_d[NB * TOTROWS];

// ============================ helpers ============================
__device__ __forceinline__ uint32_t smem_u32(const void* p) {
    uint32_t a;
    asm("{ .reg .u64 t; cvta.to.shared.u64 t, %1; cvt.u32.u64 %0, t; }"
        : "=r"(a) : "l"(p));
    return a;
}

__device__ __forceinline__ void ldsm_x4(uint32_t r[4], uint32_t addr) {
    asm volatile("ldmatrix.sync.aligned.m8n8.x4.shared.b16 {%0,%1,%2,%3}, [%4];"
                 : "=r"(r[0]), "=r"(r[1]), "=r"(r[2]), "=r"(r[3]) : "r"(addr));
}
__device__ __forceinline__ void ldsm_x4_t(uint32_t r[4], uint32_t addr) {
    asm volatile("ldmatrix.sync.aligned.m8n8.x4.trans.shared.b16 {%0,%1,%2,%3}, [%4];"
                 : "=r"(r[0]), "=r"(r[1]), "=r"(r[2]), "=r"(r[3]) : "r"(addr));
}

// D(+=) A@B : m16n8k16 fp16 -> f32
__device__ __forceinline__ void mma16816(float c[4], const uint32_t a[4],
                                         uint32_t b0, uint32_t b1) {
    asm volatile(
        "mma.sync.aligned.m16n8k16.row.col.f32.f16.f16.f32 "
        "{%0,%1,%2,%3}, {%4,%5,%6,%7}, {%8,%9}, {%0,%1,%2,%3};"
        : "+f"(c[0]), "+f"(c[1]), "+f"(c[2]), "+f"(c[3])
        : "r"(a[0]), "r"(a[1]), "r"(a[2]), "r"(a[3]), "r"(b0), "r"(b1));
}

// split two fp32 into packed fp16x2 hi and lo
__device__ __forceinline__ void split2(float x, float y, uint32_t& hi, uint32_t& lo) {
    __half hx = __float2half_rn(x);
    __half hy = __float2half_rn(y);
    __half lx = __float2half_rn(x - __half2float(hx));
    __half ly = __float2half_rn(y - __half2float(hy));
    __half2 h2 = __halves2half2(hx, hy);
    __half2 l2 = __halves2half2(lx, ly);
    hi = *(uint32_t*)&h2;
    lo = *(uint32_t*)&l2;
}

// pack two f32 (even -> low half, odd -> high half) into fp16x2
__device__ __forceinline__ uint32_t pack_f16x2(float even, float odd) {
    uint32_t d;
    asm("cvt.rn.f16x2.f32 %0, %1, %2;" : "=r"(d) : "f"(odd), "f"(even));
    return d;
}
__device__ __forceinline__ uint32_t ex2_f16x2(uint32_t a) {
    uint32_t d;
    asm("ex2.approx.f16x2 %0, %1;" : "=r"(d) : "r"(a));
    return d;
}
__device__ __forceinline__ float ex2f(float x) {
    float r;
    asm("ex2.approx.f32 %0, %1;" : "=f"(r) : "f"(x));
    return r;
}

// cp.async helpers
__device__ __forceinline__ void cp16(uint32_t dst, const void* src) {
    asm volatile("cp.async.cg.shared.global [%0], [%1], 16;" :: "r"(dst), "l"(src));
}
__device__ __forceinline__ void cp_commit() {
    asm volatile("cp.async.commit_group;" ::: "memory");
}
template <int N>
__device__ __forceinline__ void cp_wait() {
    asm volatile("cp.async.wait_group %0;" :: "n"(N) : "memory");
}

// ---------------------------------------------------------------------------
// Kernel 0: transpose W (hi only) -> g_wth [w][n=128][k=1024] fp16
// ---------------------------------------------------------------------------
__global__ __launch_bounds__(256) void split_w(
    const float* __restrict__ Wq, const float* __restrict__ Wk,
    const float* __restrict__ Wv)
{
    __shared__ float tile[32][33];
    const float* W = (blockIdx.z == 0) ? Wq : (blockIdx.z == 1) ? Wk : Wv;
    const int k0 = blockIdx.x * 32;
    const int n0 = blockIdx.y * 32;
    const int tx = threadIdx.x, ty = threadIdx.y;
    #pragma unroll
    for (int i = ty; i < 32; i += 8)
        tile[i][tx] = W[(size_t)(k0 + i) * NH + n0 + tx];
    __syncthreads();
    #pragma unroll
    for (int i = ty; i < 32; i += 8) {
        size_t idx = (size_t)blockIdx.z * 131072 + (size_t)(n0 + i) * 1024 + k0 + tx;
        g_wth[idx] = __float2half_rn(tile[tx][i]);
    }
}

// ---------------------------------------------------------------------------
// Kernel 1: QKV projection, 1-term fp16 mma.sync: D = xh @ Wh (fp32 accum).
// CTA tile M=128, N=128, K chunks of 32. grid=(256,3) y->Wq/Wk/Wv.
// q epilogue splits fp32 result into qh+ql (QK stays 2-term); k/v store hi.
// ---------------------------------------------------------------------------
#define PSTR 40                 // padded k stride (fp16 elements)
#define PBUF (128 * PSTR)       // elements per smem array
#define PROJ_SMEM_BYTES (2 * 2 * PBUF * 2)   // 2 buffers x {AH, BH}

__global__ __launch_bounds__(256) void proj_mma(const float* __restrict__ x)
{
    extern __shared__ __half psm[];
    const int t = threadIdx.x;
    const int lane = t & 31;
    const int wid = t >> 5;
    const int wm = wid & 1;
    const int wn = wid >> 1;
    const size_t m0 = (size_t)blockIdx.x * 128;
    const int wsel = blockIdx.y;
    const __half* wth = g_wth + (size_t)wsel * 131072;

    float acc[4][4][4];
    #pragma unroll
    for (int i = 0; i < 4; i++)
        #pragma unroll
        for (int j = 0; j < 4; j++)
            #pragma unroll
            for (int e = 0; e < 4; e++) acc[i][j][e] = 0.f;

    float4 sa[4];
    uint4 sbh[2];

    const int a_row[4] = { t >> 3, (t + 256) >> 3, (t + 512) >> 3, (t + 768) >> 3 };
    const int a_c4 = (t & 7) * 4;

    auto load_stage = [&](int k0) {
        #pragma unroll
        for (int p = 0; p < 4; p++)
            sa[p] = *(const float4*)&x[(m0 + a_row[p]) * NC + k0 + a_c4];
        #pragma unroll
        for (int p = 0; p < 2; p++) {
            int idx = t + p * 256;
            int row = idx >> 2, c8 = idx & 3;
            sbh[p] = *(const uint4*)&wth[(size_t)row * 1024 + k0 + c8 * 8];
        }
    };
    auto store_stage = [&](int buf) {
        __half* AH = psm + buf * 2 * PBUF;
        __half* BH = AH + PBUF;
        #pragma unroll
        for (int p = 0; p < 4; p++) {
            uint32_t h01 = pack_f16x2(sa[p].x, sa[p].y);
            uint32_t h23 = pack_f16x2(sa[p].z, sa[p].w);
            uint32_t off = a_row[p] * PSTR + a_c4;
            *(uint2*)&AH[off] = make_uint2(h01, h23);
        }
        #pragma unroll
        for (int p = 0; p < 2; p++) {
            int idx = t + p * 256;
            int row = idx >> 2, c8 = idx & 3;
            *(uint4*)&BH[row * PSTR + c8 * 8] = sbh[p];
        }
    };

    const uint32_t smbase = smem_u32(psm);
    const int lr = lane & 15;
    const int lc = (lane >> 4) * 8;

    auto compute = [&](int buf) {
        const uint32_t AHb = smbase + (buf * 2 * PBUF) * 2;
        const uint32_t BHb = AHb + PBUF * 2;
        #pragma unroll
        for (int ks = 0; ks < 2; ks++) {
            uint32_t ah[4][4];
            #pragma unroll
            for (int i = 0; i < 4; i++) {
                uint32_t off = ((wm * 64 + i * 16 + lr) * PSTR + ks * 16 + lc) * 2;
                ldsm_x4(ah[i], AHb + off);
            }
            #pragma unroll
            for (int jj = 0; jj < 2; jj++) {
                uint32_t off = ((wn * 32 + jj * 16 + lr) * PSTR + ks * 16 + lc) * 2;
                uint32_t bh[4];
                ldsm_x4(bh, BHb + off);
                #pragma unroll
                for (int i = 0; i < 4; i++) {
                    mma16816(acc[i][2 * jj],     ah[i], bh[0], bh[2]);
                    mma16816(acc[i][2 * jj + 1], ah[i], bh[1], bh[3]);
                }
            }
        }
    };

    load_stage(0);
    for (int c = 0; c < 32; c++) {
        store_stage(c & 1);
        __syncthreads();
        if (c + 1 < 32) load_stage((c + 1) * 32);
        compute(c & 1);
    }

    // epilogue: q pre-scaled by log2(e)/sqrt(128), split hi/lo; k/v hi only.
    const float scale = (wsel == 0) ? (0.08838834764831843f * 1.4426950408889634f) : 1.0f;
    __half* DH = (wsel == 0) ? g_qh : (wsel == 1) ? g_kh : g_vh;
    #pragma unroll
    for (int i = 0; i < 4; i++) {
        #pragma unroll
        for (int j = 0; j < 4; j++) {
            const int col = wn * 32 + j * 8 + 2 * (lane & 3);
            #pragma unroll
            for (int z = 0; z < 2; z++) {
                const size_t row = m0 + wm * 64 + i * 16 + (lane >> 2) + 8 * z;
                if (wsel == 0) {
                    uint32_t hi, lo;
                    split2(acc[i][j][2 * z] * scale, acc[i][j][2 * z + 1] * scale, hi, lo);
                    *(uint32_t*)&g_qh[row * NH + col] = hi;
                    *(uint32_t*)&g_ql[row * NH + col] = lo;
                } else {
                    *(uint32_t*)&DH[row * NH + col] =
                        pack_f16x2(acc[i][j][2 * z], acc[i][j][2 * z + 1]);
                }
            }
        }
    }
}

// ---------------------------------------------------------------------------
// Kernel 2: causal flash attention, fp16 mma.sync, packed-fp16 exp2 softmax.
// QK 2-term (S = (Qh+Ql)·Kh), PV 1-term (P exact fp16, V hi only).
// 128-row Q tiles, 8 warps, cp.async double-buffered K/V.
// V carries 8 constant ones-columns (cols 128..135) -> row-sums via MMA.
// ---------------------------------------------------------------------------
#define ASTR 136                        // Q/K padded stride (fp16 elems)
#define VSTR 152                        // V padded stride (128 data + 16 ones/pad)
#define QTILE (128 * ASTR)              // 17408
#define KTILE (64 * ASTR)               // 8704
#define VTILE (64 * VSTR)               // 9728
#define BUFSZ (KTILE + VTILE)           // 18432 elems per buffer
#define ATTN_SMEM_BYTES ((2 * QTILE + 2 * BUFSZ) * 2)   // 143360 B

__global__ __launch_bounds__(256) void attn_mma()
{
    extern __shared__ __half asm_[];
    const int blk = blockIdx.x;
    const int qb  = 7 - blk / 60;       // heavy tiles first
    const int t2  = blk % 60;
    const int b   = t2 / 15;
    const int cs  = t2 % 15;
    int cfg, seg;
    if (cs < 8)       { cfg = 0; seg = cs; }
    else if (cs < 12) { cfg = 1; seg = cs - 8; }
    else if (cs < 14) { cfg = 2; seg = cs - 12; }
    else              { cfg = 3; seg = 0; }
    const int rr = 1 << cfg;
    const int ww = 1024 << cfg;

    const int t = threadIdx.x;
    const int lane = t & 31;
    const int w = t >> 5;
    const size_t tok0 = (size_t)b * NN + seg * ww;

    const uint32_t sb = smem_u32(asm_);
    const uint32_t QHb = sb;
    const uint32_t QLb = sb + QTILE * 2;

    auto kh_off = [](int buf) { return 2 * QTILE + buf * BUFSZ; };
    auto vh_off = [](int buf) { return 2 * QTILE + buf * BUFSZ + KTILE; };

    // ---- constant ones-columns in VH (cols 128..135 = 1, 136..143 = 0) ----
    for (int i = t; i < 2 * 64 * 16; i += 256) {
        int buf = i >> 10;
        int r = (i & 1023) >> 4;
        int c = i & 15;
        asm_[vh_off(buf) + r * VSTR + 128 + c] = (c < 8) ? __float2half(1.0f)
                                                         : __float2half(0.0f);
    }

    // ---- issue Q tile fill (hi/lo) via cp.async : part of group 0 ----
    #pragma unroll
    for (int i = 0; i < 8; i++) {
        int idx = t + i * 256;
        int row = idx >> 4;
        int c = idx & 15;
        size_t src = (tok0 + (size_t)(qb * 128 + row) * rr) * NH + c * 8;
        uint32_t d = (row * ASTR + c * 8) * 2;
        cp16(QHb + d, g_qh + src);
        cp16(QLb + d, g_ql + src);
    }

    auto issue_kv = [&](int kt, int buf) {
        #pragma unroll
        for (int i = 0; i < 4; i++) {
            int idx = t + i * 256;
            int row = idx >> 4;
            int c = idx & 15;
            size_t src = (tok0 + (size_t)(kt * 64 + row) * rr) * NH + c * 8;
            cp16(sb + (kh_off(buf) + row * ASTR + c * 8) * 2, g_kh + src);
            cp16(sb + (vh_off(buf) + row * VSTR + c * 8) * 2, g_vh + src);
        }
    };

    const int L = 2 * qb + 1;
    issue_kv(0, 0);
    cp_commit();
    issue_kv(1, 1);
    cp_commit();

    float o[16][4];
    float osum[4] = {0.f, 0.f, 0.f, 0.f};   // l accumulator (ones-column MMA)
    #pragma unroll
    for (int j = 0; j < 16; j++)
        #pragma unroll
        for (int e = 0; e < 4; e++) o[j][e] = 0.f;
    float m_i[2] = { -INFINITY, -INFINITY };

    const int lr = lane & 15;
    const int lc = (lane >> 4) * 8;

    for (int kt = 0; kt <= L; kt++) {
        if (kt < L) cp_wait<1>(); else cp_wait<0>();
        __syncthreads();

        const int buf = kt & 1;
        const uint32_t KHb = sb + kh_off(buf) * 2;
        const uint32_t VHb = sb + vh_off(buf) * 2;

        const bool active = (qb * 128 + w * 16 + 15) >= kt * 64;
        if (active) {
            // ---- S = (Qh+Ql) @ Kh^T (log2 domain; 2-term) ----
            float s[8][4];
            #pragma unroll
            for (int j = 0; j < 8; j++)
                #pragma unroll
                for (int e = 0; e < 4; e++) s[j][e] = 0.f;

            #pragma unroll
            for (int ks = 0; ks < 8; ks++) {
                uint32_t qh[4], ql[4];
                {
                    uint32_t off = ((w * 16 + lr) * ASTR + ks * 16 + lc) * 2;
                    ldsm_x4(qh, QHb + off);
                    ldsm_x4(ql, QLb + off);
                }
                #pragma unroll
                for (int jj = 0; jj < 4; jj++) {
                    uint32_t off = ((jj * 16 + lr) * ASTR + ks * 16 + lc) * 2;
                    uint32_t kh[4];
                    ldsm_x4(kh, KHb + off);
                    mma16816(s[2 * jj],     qh, kh[0], kh[2]);
                    mma16816(s[2 * jj],     ql, kh[0], kh[2]);
                    mma16816(s[2 * jj + 1], qh, kh[1], kh[3]);
                    mma16816(s[2 * jj + 1], ql, kh[1], kh[3]);
                }
            }

            // ---- causal mask ----
            if (kt >= 2 * qb) {
                #pragma unroll
                for (int j = 0; j < 8; j++)
                    #pragma unroll
                    for (int z = 0; z < 2; z++) {
                        int gq = qb * 128 + w * 16 + (lane >> 2) + 8 * z;
                        int gk = kt * 64 + j * 8 + 2 * (lane & 3);
                        if (gk > gq)     s[j][2 * z]     = -INFINITY;
                        if (gk + 1 > gq) s[j][2 * z + 1] = -INFINITY;
                    }
            }

            // ---- online softmax: max + rescale (exp2 domain) ----
            float mn[2];
            #pragma unroll
            for (int z = 0; z < 2; z++) {
                float mx = -INFINITY;
                #pragma unroll
                for (int j = 0; j < 8; j++)
                    mx = fmaxf(mx, fmaxf(s[j][2 * z], s[j][2 * z + 1]));
                mx = fmaxf(mx, __shfl_xor_sync(0xffffffffu, mx, 1));
                mx = fmaxf(mx, __shfl_xor_sync(0xffffffffu, mx, 2));
                mn[z] = fmaxf(m_i[z], mx);
                float sc = ex2f(m_i[z] - mn[z]);
                m_i[z] = mn[z];
                #pragma unroll
                for (int j = 0; j < 16; j++) {
                    o[j][2 * z] *= sc;
                    o[j][2 * z + 1] *= sc;
                }
                osum[2 * z] *= sc;
                osum[2 * z + 1] *= sc;
            }

            // ---- P = exp2(S - m) packed fp16x2 ----
            uint32_t p16[8][2];
            #pragma unroll
            for (int j = 0; j < 8; j++) {
                p16[j][0] = ex2_f16x2(pack_f16x2(s[j][0] - mn[0], s[j][1] - mn[0]));
                p16[j][1] = ex2_f16x2(pack_f16x2(s[j][2] - mn[1], s[j][3] - mn[1]));
            }

            // ---- O += P @ Vh (1-term) + ones-column row sums ----
            #pragma unroll
            for (int kk = 0; kk < 4; kk++) {
                const uint32_t a[4] = { p16[2 * kk][0], p16[2 * kk][1],
                                        p16[2 * kk + 1][0], p16[2 * kk + 1][1] };
                #pragma unroll
                for (int jj = 0; jj < 8; jj++) {
                    uint32_t off = ((kk * 16 + lr) * VSTR + jj * 16 + lc) * 2;
                    uint32_t vh[4];
                    ldsm_x4_t(vh, VHb + off);
                    mma16816(o[2 * jj],     a, vh[0], vh[1]);
                    mma16816(o[2 * jj + 1], a, vh[2], vh[3]);
                }
                uint32_t vs[4];
                ldsm_x4_t(vs, VHb + ((kk * 16 + lr) * VSTR + 128 + lc) * 2);
                mma16816(osum, a, vs[0], vs[1]);
            }
        }

        __syncthreads();
        if (kt + 2 <= L) {
            issue_kv(kt + 2, kt & 1);
            cp_commit();
        }
    }

    // ---- epilogue: normalize, write o and denom = l * 2^m ----
    const int cbase = 16384 - (16384 >> cfg);
    const size_t obase = (size_t)b * TOTROWS + cbase + seg * 1024 + qb * 128;
    #pragma unroll
    for (int z = 0; z < 2; z++) {
        const size_t row = obase + w * 16 + (lane >> 2) + 8 * z;
        const float l = osum[2 * z];
        const float inv = 1.0f / l;
        #pragma unroll
        for (int j = 0; j < 16; j++) {
            const int col = j * 8 + 2 * (lane & 3);
            *(float2*)&g_o[row * NH + col] =
                make_float2(o[j][2 * z] * inv, o[j][2 * z + 1] * inv);
        }
        if ((lane & 3) == 0)
            g_d[row] = l * exp2f(m_i[z]);
    }
}

// ---------------------------------------------------------------------------
// Kernel 3: cross-config combine. One warp per (b, p); lane covers 4 h.
// ---------------------------------------------------------------------------
__global__ __launch_bounds__(256) void combine_kernel(float* __restrict__ out)
{
    const int gw = (blockIdx.x * blockDim.x + threadIdx.x) >> 5;
    const int lane = threadIdx.x & 31;
    if (gw >= NB * NN) return;
    const int b = gw >> 13;
    const int p = gw & (NN - 1);

    size_t rows[4];
    float dens[4];
    int cnt = 0;
    float dsum = 0.f;
    #pragma unroll
    for (int i = 0; i < 4; i++) {
        if ((p & ((1 << i) - 1)) == 0) {
            int s = p >> (10 + i);
            int j = (p & ((1024 << i) - 1)) >> i;
            int cbase = 16384 - (16384 >> i);
            size_t row = (size_t)b * TOTROWS + cbase + s * 1024 + j;
            float d = g_d[row];
            rows[cnt] = row;
            dens[cnt] = d;
            dsum += d;
            cnt++;
        }
    }

    const int c = lane * 4;
    float4 acc = make_float4(0.f, 0.f, 0.f, 0.f);
    for (int q = 0; q < cnt; q++) {
        float wgt = dens[q] / dsum;
        float4 ov = *(const float4*)&g_o[rows[q] * NH + c];
        acc.x += ov.x * wgt;
        acc.y += ov.y * wgt;
        acc.z += ov.z * wgt;
        acc.w += ov.w * wgt;
    }
    *(float4*)&out[((size_t)b * NN + p) * NH + c] = acc;
}

// ---------------------------------------------------------------------------
extern "C" void kernel_launch(void* const* d_in, const int* in_sizes, int n_in,
                              void* d_out, int out_size)
{
    const float* x  = (const float*)d_in[0];
    const float* Wq = (const float*)d_in[1];
    const float* Wk = (const float*)d_in[2];
    const float* Wv = (const float*)d_in[3];
    float* out = (float*)d_out;

    cudaFuncSetAttribute((const void*)proj_mma,
                         cudaFuncAttributeMaxDynamicSharedMemorySize, PROJ_SMEM_BYTES);
    cudaFuncSetAttribute((const void*)attn_mma,
                         cudaFuncAttributeMaxDynamicSharedMemorySize, ATTN_SMEM_BYTES);

    split_w<<<dim3(32, 4, 3), dim3(32, 8)>>>(Wq, Wk, Wv);
    proj_mma<<<dim3(256, 3), 256, PROJ_SMEM_BYTES>>>(x);
    attn_mma<<<480, 256, ATTN_SMEM_BYTES>>>();
    combine_kernel<<<(NB * NN * 32 + 255) / 256, 256>>>(out);
}

// round 9
// speedup vs baseline: 6.8189x; 1.1522x over previous
#include <cuda_runtime.h>
#include <cuda_fp16.h>
#include <math.h>
#include <stdint.h>

// Problem constants
#define NB 4
#define NN 8192
#define NC 1024
#define NH 128
#define TOTROWS 15360   // 8192 + 4096 + 2048 + 1024 scratch rows per batch

// Scratch (device globals)
__device__ __half g_qh[NB * NN * NH];
__device__ __half g_kh[NB * NN * NH];
__device__ __half g_vh[NB * NN * NH];
__device__ __half g_wth[3 * 128 * 1024];   // W^T hi [w][n][k]
__device__ __half g_o[(size_t)NB * TOTROWS * NH];
__device__ float g_d[NB * TOTROWS];

// ============================ helpers ============================
__device__ __forceinline__ uint32_t smem_u32(const void* p) {
    uint32_t a;
    asm("{ .reg .u64 t; cvta.to.shared.u64 t, %1; cvt.u32.u64 %0, t; }"
        : "=r"(a) : "l"(p));
    return a;
}

__device__ __forceinline__ void ldsm_x4(uint32_t r[4], uint32_t addr) {
    asm volatile("ldmatrix.sync.aligned.m8n8.x4.shared.b16 {%0,%1,%2,%3}, [%4];"
                 : "=r"(r[0]), "=r"(r[1]), "=r"(r[2]), "=r"(r[3]) : "r"(addr));
}
__device__ __forceinline__ void ldsm_x4_t(uint32_t r[4], uint32_t addr) {
    asm volatile("ldmatrix.sync.aligned.m8n8.x4.trans.shared.b16 {%0,%1,%2,%3}, [%4];"
                 : "=r"(r[0]), "=r"(r[1]), "=r"(r[2]), "=r"(r[3]) : "r"(addr));
}

// D(+=) A@B : m16n8k16 fp16 -> f32
__device__ __forceinline__ void mma16816(float c[4], const uint32_t a[4],
                                         uint32_t b0, uint32_t b1) {
    asm volatile(
        "mma.sync.aligned.m16n8k16.row.col.f32.f16.f16.f32 "
        "{%0,%1,%2,%3}, {%4,%5,%6,%7}, {%8,%9}, {%0,%1,%2,%3};"
        : "+f"(c[0]), "+f"(c[1]), "+f"(c[2]), "+f"(c[3])
        : "r"(a[0]), "r"(a[1]), "r"(a[2]), "r"(a[3]), "r"(b0), "r"(b1));
}

// pack two f32 (even -> low half, odd -> high half) into fp16x2
__device__ __forceinline__ uint32_t pack_f16x2(float even, float odd) {
    uint32_t d;
    asm("cvt.rn.f16x2.f32 %0, %1, %2;" : "=r"(d) : "f"(odd), "f"(even));
    return d;
}
__device__ __forceinline__ uint32_t ex2_f16x2(uint32_t a) {
    uint32_t d;
    asm("ex2.approx.f16x2 %0, %1;" : "=r"(d) : "r"(a));
    return d;
}
__device__ __forceinline__ float ex2f(float x) {
    float r;
    asm("ex2.approx.f32 %0, %1;" : "=f"(r) : "f"(x));
    return r;
}

// cp.async helpers
__device__ __forceinline__ void cp16(uint32_t dst, const void* src) {
    asm volatile("cp.async.cg.shared.global [%0], [%1], 16;" :: "r"(dst), "l"(src));
}
__device__ __forceinline__ void cp_commit() {
    asm volatile("cp.async.commit_group;" ::: "memory");
}
template <int N>
__device__ __forceinline__ void cp_wait() {
    asm volatile("cp.async.wait_group %0;" :: "n"(N) : "memory");
}

// ---------------------------------------------------------------------------
// Kernel 0: transpose W (hi only) -> g_wth [w][n=128][k=1024] fp16
// ---------------------------------------------------------------------------
__global__ __launch_bounds__(256) void split_w(
    const float* __restrict__ Wq, const float* __restrict__ Wk,
    const float* __restrict__ Wv)
{
    __shared__ float tile[32][33];
    const float* W = (blockIdx.z == 0) ? Wq : (blockIdx.z == 1) ? Wk : Wv;
    const int k0 = blockIdx.x * 32;
    const int n0 = blockIdx.y * 32;
    const int tx = threadIdx.x, ty = threadIdx.y;
    #pragma unroll
    for (int i = ty; i < 32; i += 8)
        tile[i][tx] = W[(size_t)(k0 + i) * NH + n0 + tx];
    __syncthreads();
    #pragma unroll
    for (int i = ty; i < 32; i += 8) {
        size_t idx = (size_t)blockIdx.z * 131072 + (size_t)(n0 + i) * 1024 + k0 + tx;
        g_wth[idx] = __float2half_rn(tile[tx][i]);
    }
}

// ---------------------------------------------------------------------------
// Kernel 1: QKV projection, 1-term fp16 mma.sync: D = xh @ Wh (fp32 accum).
// CTA tile M=128, N=128, K chunks of 32. grid=(256,3) y->Wq/Wk/Wv.
// All outputs stored as single fp16 (q pre-scaled by log2(e)/sqrt(128)).
// ---------------------------------------------------------------------------
#define PSTR 40                 // padded k stride (fp16 elements)
#define PBUF (128 * PSTR)       // elements per smem array
#define PROJ_SMEM_BYTES (2 * 2 * PBUF * 2)   // 2 buffers x {AH, BH}

__global__ __launch_bounds__(256) void proj_mma(const float* __restrict__ x)
{
    extern __shared__ __half psm[];
    const int t = threadIdx.x;
    const int lane = t & 31;
    const int wid = t >> 5;
    const int wm = wid & 1;
    const int wn = wid >> 1;
    const size_t m0 = (size_t)blockIdx.x * 128;
    const int wsel = blockIdx.y;
    const __half* wth = g_wth + (size_t)wsel * 131072;

    float acc[4][4][4];
    #pragma unroll
    for (int i = 0; i < 4; i++)
        #pragma unroll
        for (int j = 0; j < 4; j++)
            #pragma unroll
            for (int e = 0; e < 4; e++) acc[i][j][e] = 0.f;

    float4 sa[4];
    uint4 sbh[2];

    const int a_row[4] = { t >> 3, (t + 256) >> 3, (t + 512) >> 3, (t + 768) >> 3 };
    const int a_c4 = (t & 7) * 4;

    auto load_stage = [&](int k0) {
        #pragma unroll
        for (int p = 0; p < 4; p++)
            sa[p] = *(const float4*)&x[(m0 + a_row[p]) * NC + k0 + a_c4];
        #pragma unroll
        for (int p = 0; p < 2; p++) {
            int idx = t + p * 256;
            int row = idx >> 2, c8 = idx & 3;
            sbh[p] = *(const uint4*)&wth[(size_t)row * 1024 + k0 + c8 * 8];
        }
    };
    auto store_stage = [&](int buf) {
        __half* AH = psm + buf * 2 * PBUF;
        __half* BH = AH + PBUF;
        #pragma unroll
        for (int p = 0; p < 4; p++) {
            uint32_t h01 = pack_f16x2(sa[p].x, sa[p].y);
            uint32_t h23 = pack_f16x2(sa[p].z, sa[p].w);
            uint32_t off = a_row[p] * PSTR + a_c4;
            *(uint2*)&AH[off] = make_uint2(h01, h23);
        }
        #pragma unroll
        for (int p = 0; p < 2; p++) {
            int idx = t + p * 256;
            int row = idx >> 2, c8 = idx & 3;
            *(uint4*)&BH[row * PSTR + c8 * 8] = sbh[p];
        }
    };

    const uint32_t smbase = smem_u32(psm);
    const int lr = lane & 15;
    const int lc = (lane >> 4) * 8;

    auto compute = [&](int buf) {
        const uint32_t AHb = smbase + (buf * 2 * PBUF) * 2;
        const uint32_t BHb = AHb + PBUF * 2;
        #pragma unroll
        for (int ks = 0; ks < 2; ks++) {
            uint32_t ah[4][4];
            #pragma unroll
            for (int i = 0; i < 4; i++) {
                uint32_t off = ((wm * 64 + i * 16 + lr) * PSTR + ks * 16 + lc) * 2;
                ldsm_x4(ah[i], AHb + off);
            }
            #pragma unroll
            for (int jj = 0; jj < 2; jj++) {
                uint32_t off = ((wn * 32 + jj * 16 + lr) * PSTR + ks * 16 + lc) * 2;
                uint32_t bh[4];
                ldsm_x4(bh, BHb + off);
                #pragma unroll
                for (int i = 0; i < 4; i++) {
                    mma16816(acc[i][2 * jj],     ah[i], bh[0], bh[2]);
                    mma16816(acc[i][2 * jj + 1], ah[i], bh[1], bh[3]);
                }
            }
        }
    };

    load_stage(0);
    for (int c = 0; c < 32; c++) {
        store_stage(c & 1);
        __syncthreads();
        if (c + 1 < 32) load_stage((c + 1) * 32);
        compute(c & 1);
    }

    // epilogue: q pre-scaled by log2(e)/sqrt(128); single fp16 store
    const float scale = (wsel == 0) ? (0.08838834764831843f * 1.4426950408889634f) : 1.0f;
    __half* DH = (wsel == 0) ? g_qh : (wsel == 1) ? g_kh : g_vh;
    #pragma unroll
    for (int i = 0; i < 4; i++) {
        #pragma unroll
        for (int j = 0; j < 4; j++) {
            const int col = wn * 32 + j * 8 + 2 * (lane & 3);
            #pragma unroll
            for (int z = 0; z < 2; z++) {
                const size_t row = m0 + wm * 64 + i * 16 + (lane >> 2) + 8 * z;
                *(uint32_t*)&DH[row * NH + col] =
                    pack_f16x2(acc[i][j][2 * z] * scale, acc[i][j][2 * z + 1] * scale);
            }
        }
    }
}

// ---------------------------------------------------------------------------
// Kernel 2: causal flash attention, fp16 mma.sync, packed-fp16 exp2 softmax.
// QK 1-term (S = Q·K), PV 1-term. 128-row Q tiles, 8 warps,
// cp.async double-buffered K/V. smem 108.5KB -> 2 CTAs/SM.
// V carries 8 constant ones-columns (cols 128..135) -> row-sums via MMA.
// Output o stored fp16.
// ---------------------------------------------------------------------------
#define ASTR 136                        // Q/K padded stride (fp16 elems)
#define VSTR 152                        // V padded stride (128 data + 16 ones/pad)
#define QTILE (128 * ASTR)              // 17408
#define KTILE (64 * ASTR)               // 8704
#define VTILE (64 * VSTR)               // 9728
#define BUFSZ (KTILE + VTILE)           // 18432 elems per buffer
#define ATTN_SMEM_BYTES ((QTILE + 2 * BUFSZ) * 2)   // 108544 B

__global__ __launch_bounds__(256) void attn_mma()
{
    extern __shared__ __half asm_[];
    const int blk = blockIdx.x;
    const int qb  = 7 - blk / 60;       // heavy tiles first
    const int t2  = blk % 60;
    const int b   = t2 / 15;
    const int cs  = t2 % 15;
    int cfg, seg;
    if (cs < 8)       { cfg = 0; seg = cs; }
    else if (cs < 12) { cfg = 1; seg = cs - 8; }
    else if (cs < 14) { cfg = 2; seg = cs - 12; }
    else              { cfg = 3; seg = 0; }
    const int rr = 1 << cfg;
    const int ww = 1024 << cfg;

    const int t = threadIdx.x;
    const int lane = t & 31;
    const int w = t >> 5;
    const size_t tok0 = (size_t)b * NN + seg * ww;

    const uint32_t sb = smem_u32(asm_);
    const uint32_t QHb = sb;

    auto kh_off = [](int buf) { return QTILE + buf * BUFSZ; };
    auto vh_off = [](int buf) { return QTILE + buf * BUFSZ + KTILE; };

    // ---- constant ones-columns in VH (cols 128..135 = 1, 136..143 = 0) ----
    for (int i = t; i < 2 * 64 * 16; i += 256) {
        int buf = i >> 10;
        int r = (i & 1023) >> 4;
        int c = i & 15;
        asm_[vh_off(buf) + r * VSTR + 128 + c] = (c < 8) ? __float2half(1.0f)
                                                         : __float2half(0.0f);
    }

    // ---- issue Q tile fill via cp.async : part of group 0 ----
    #pragma unroll
    for (int i = 0; i < 8; i++) {
        int idx = t + i * 256;
        int row = idx >> 4;
        int c = idx & 15;
        size_t src = (tok0 + (size_t)(qb * 128 + row) * rr) * NH + c * 8;
        if (i < 8) {   // all 2048 iterations used for Q (128 rows x 16 chunks)
            uint32_t d = (row * ASTR + c * 8) * 2;
            cp16(QHb + d, g_qh + src);
        }
    }

    auto issue_kv = [&](int kt, int buf) {
        #pragma unroll
        for (int i = 0; i < 4; i++) {
            int idx = t + i * 256;
            int row = idx >> 4;
            int c = idx & 15;
            size_t src = (tok0 + (size_t)(kt * 64 + row) * rr) * NH + c * 8;
            cp16(sb + (kh_off(buf) + row * ASTR + c * 8) * 2, g_kh + src);
            cp16(sb + (vh_off(buf) + row * VSTR + c * 8) * 2, g_vh + src);
        }
    };

    const int L = 2 * qb + 1;
    issue_kv(0, 0);
    cp_commit();
    issue_kv(1, 1);
    cp_commit();

    float o[16][4];
    float osum[4] = {0.f, 0.f, 0.f, 0.f};   // l accumulator (ones-column MMA)
    #pragma unroll
    for (int j = 0; j < 16; j++)
        #pragma unroll
        for (int e = 0; e < 4; e++) o[j][e] = 0.f;
    float m_i[2] = { -INFINITY, -INFINITY };

    const int lr = lane & 15;
    const int lc = (lane >> 4) * 8;

    for (int kt = 0; kt <= L; kt++) {
        if (kt < L) cp_wait<1>(); else cp_wait<0>();
        __syncthreads();

        const int buf = kt & 1;
        const uint32_t KHb = sb + kh_off(buf) * 2;
        const uint32_t VHb = sb + vh_off(buf) * 2;

        const bool active = (qb * 128 + w * 16 + 15) >= kt * 64;
        if (active) {
            // ---- S = Q @ K^T (log2 domain; 1-term) ----
            float s[8][4];
            #pragma unroll
            for (int j = 0; j < 8; j++)
                #pragma unroll
                for (int e = 0; e < 4; e++) s[j][e] = 0.f;

            #pragma unroll
            for (int ks = 0; ks < 8; ks++) {
                uint32_t qh[4];
                {
                    uint32_t off = ((w * 16 + lr) * ASTR + ks * 16 + lc) * 2;
                    ldsm_x4(qh, QHb + off);
                }
                #pragma unroll
                for (int jj = 0; jj < 4; jj++) {
                    uint32_t off = ((jj * 16 + lr) * ASTR + ks * 16 + lc) * 2;
                    uint32_t kh[4];
                    ldsm_x4(kh, KHb + off);
                    mma16816(s[2 * jj],     qh, kh[0], kh[2]);
                    mma16816(s[2 * jj + 1], qh, kh[1], kh[3]);
                }
            }

            // ---- causal mask ----
            if (kt >= 2 * qb) {
                #pragma unroll
                for (int j = 0; j < 8; j++)
                    #pragma unroll
                    for (int z = 0; z < 2; z++) {
                        int gq = qb * 128 + w * 16 + (lane >> 2) + 8 * z;
                        int gk = kt * 64 + j * 8 + 2 * (lane & 3);
                        if (gk > gq)     s[j][2 * z]     = -INFINITY;
                        if (gk + 1 > gq) s[j][2 * z + 1] = -INFINITY;
                    }
            }

            // ---- online softmax: max + rescale (exp2 domain) ----
            float mn[2];
            #pragma unroll
            for (int z = 0; z < 2; z++) {
                float mx = -INFINITY;
                #pragma unroll
                for (int j = 0; j < 8; j++)
                    mx = fmaxf(mx, fmaxf(s[j][2 * z], s[j][2 * z + 1]));
                mx = fmaxf(mx, __shfl_xor_sync(0xffffffffu, mx, 1));
                mx = fmaxf(mx, __shfl_xor_sync(0xffffffffu, mx, 2));
                mn[z] = fmaxf(m_i[z], mx);
                float sc = ex2f(m_i[z] - mn[z]);
                m_i[z] = mn[z];
                #pragma unroll
                for (int j = 0; j < 16; j++) {
                    o[j][2 * z] *= sc;
                    o[j][2 * z + 1] *= sc;
                }
                osum[2 * z] *= sc;
                osum[2 * z + 1] *= sc;
            }

            // ---- P = exp2(S - m) packed fp16x2 ----
            uint32_t p16[8][2];
            #pragma unroll
            for (int j = 0; j < 8; j++) {
                p16[j][0] = ex2_f16x2(pack_f16x2(s[j][0] - mn[0], s[j][1] - mn[0]));
                p16[j][1] = ex2_f16x2(pack_f16x2(s[j][2] - mn[1], s[j][3] - mn[1]));
            }

            // ---- O += P @ Vh (1-term) + ones-column row sums ----
            #pragma unroll
            for (int kk = 0; kk < 4; kk++) {
                const uint32_t a[4] = { p16[2 * kk][0], p16[2 * kk][1],
                                        p16[2 * kk + 1][0], p16[2 * kk + 1][1] };
                #pragma unroll
                for (int jj = 0; jj < 8; jj++) {
                    uint32_t off = ((kk * 16 + lr) * VSTR + jj * 16 + lc) * 2;
                    uint32_t vh[4];
                    ldsm_x4_t(vh, VHb + off);
                    mma16816(o[2 * jj],     a, vh[0], vh[1]);
                    mma16816(o[2 * jj + 1], a, vh[2], vh[3]);
                }
                uint32_t vs[4];
                ldsm_x4_t(vs, VHb + ((kk * 16 + lr) * VSTR + 128 + lc) * 2);
                mma16816(osum, a, vs[0], vs[1]);
            }
        }

        __syncthreads();
        if (kt + 2 <= L) {
            issue_kv(kt + 2, kt & 1);
            cp_commit();
        }
    }

    // ---- epilogue: normalize, write o (fp16) and denom = l * 2^m ----
    const int cbase = 16384 - (16384 >> cfg);
    const size_t obase = (size_t)b * TOTROWS + cbase + seg * 1024 + qb * 128;
    #pragma unroll
    for (int z = 0; z < 2; z++) {
        const size_t row = obase + w * 16 + (lane >> 2) + 8 * z;
        const float l = osum[2 * z];
        const float inv = 1.0f / l;
        #pragma unroll
        for (int j = 0; j < 16; j++) {
            const int col = j * 8 + 2 * (lane & 3);
            *(uint32_t*)&g_o[row * NH + col] =
                pack_f16x2(o[j][2 * z] * inv, o[j][2 * z + 1] * inv);
        }
        if ((lane & 3) == 0)
            g_d[row] = l * exp2f(m_i[z]);
    }
}

// ---------------------------------------------------------------------------
// Kernel 3: cross-config combine. One warp per (b, p); lane covers 4 h.
// ---------------------------------------------------------------------------
__global__ __launch_bounds__(256) void combine_kernel(float* __restrict__ out)
{
    const int gw = (blockIdx.x * blockDim.x + threadIdx.x) >> 5;
    const int lane = threadIdx.x & 31;
    if (gw >= NB * NN) return;
    const int b = gw >> 13;
    const int p = gw & (NN - 1);

    size_t rows[4];
    float dens[4];
    int cnt = 0;
    float dsum = 0.f;
    #pragma unroll
    for (int i = 0; i < 4; i++) {
        if ((p & ((1 << i) - 1)) == 0) {
            int s = p >> (10 + i);
            int j = (p & ((1024 << i) - 1)) >> i;
            int cbase = 16384 - (16384 >> i);
            size_t row = (size_t)b * TOTROWS + cbase + s * 1024 + j;
            float d = g_d[row];
            rows[cnt] = row;
            dens[cnt] = d;
            dsum += d;
            cnt++;
        }
    }

    const int c = lane * 4;
    float4 acc = make_float4(0.f, 0.f, 0.f, 0.f);
    for (int q = 0; q < cnt; q++) {
        float wgt = dens[q] / dsum;
        uint2 pk = *(const uint2*)&g_o[rows[q] * NH + c];
        float2 v01 = __half22float2(*(__half2*)&pk.x);
        float2 v23 = __half22float2(*(__half2*)&pk.y);
        acc.x += v01.x * wgt;
        acc.y += v01.y * wgt;
        acc.z += v23.x * wgt;
        acc.w += v23.y * wgt;
    }
    *(float4*)&out[((size_t)b * NN + p) * NH + c] = acc;
}

// ---------------------------------------------------------------------------
extern "C" void kernel_launch(void* const* d_in, const int* in_sizes, int n_in,
                              void* d_out, int out_size)
{
    const float* x  = (const float*)d_in[0];
    const float* Wq = (const float*)d_in[1];
    const float* Wk = (const float*)d_in[2];
    const float* Wv = (const float*)d_in[3];
    float* out = (float*)d_out;

    cudaFuncSetAttribute((const void*)proj_mma,
                         cudaFuncAttributeMaxDynamicSharedMemorySize, PROJ_SMEM_BYTES);
    cudaFuncSetAttribute((const void*)attn_mma,
                         cudaFuncAttributeMaxDynamicSharedMemorySize, ATTN_SMEM_BYTES);

    split_w<<<dim3(32, 4, 3), dim3(32, 8)>>>(Wq, Wk, Wv);
    proj_mma<<<dim3(256, 3), 256, PROJ_SMEM_BYTES>>>(x);
    attn_mma<<<480, 256, ATTN_SMEM_BYTES>>>();
    combine_kernel<<<(NB * NN * 32 + 255) / 256, 256>>>(out);
}